// round 11
// baseline (speedup 1.0000x reference)
#include <cuda_runtime.h>
#include <cuda_bf16.h>
#include <cstdint>

// ---------------- STDP constants ----------------
#define A_PLUS      0.01f
#define A_MINUS     0.01f
#define W_MAXV      1.0f
#define W_MINV      0.0f
#define TARGET_RATE 0.1f
#define HOMEO       0.001f
#define RATE_ALPHA  0.01f
#define DECAYF      0.9512294245007140f   // exp(-1/20)

// ---------------- fixed shapes ----------------
#define BB    1024
#define PREN  4096
#define POSTN 4096
#define K1    2048
#define RATE_CHUNKS 32

// ---------------- device scratch ----------------
__device__ __align__(128) __nv_bfloat16 g_A   [(size_t)POSTN * K1];
__device__ __align__(128) __nv_bfloat16 g_Bm  [(size_t)PREN  * K1];
__device__ __align__(128) __nv_bfloat16 g_preb[(size_t)BB    * PREN];
__device__ __align__(128) __nv_bfloat16 g_Wb  [(size_t)POSTN * PREN];
__device__ float g_rate_partial[RATE_CHUNKS * POSTN];
__device__ int   g_trace_nz;   // set by prep_ew; reset by gemm2 (after all readers)

// ============================================================
// asm helpers
// ============================================================
__device__ __forceinline__ uint32_t smem_u32(const void* p) {
    uint32_t a;
    asm("{ .reg .u64 t; cvta.to.shared.u64 t, %1; cvt.u32.u64 %0, t; }" : "=r"(a) : "l"(p));
    return a;
}
__device__ __forceinline__ void ldsm4(uint32_t& r0, uint32_t& r1, uint32_t& r2, uint32_t& r3,
                                      uint32_t addr) {
    asm volatile("ldmatrix.sync.aligned.m8n8.x4.shared.b16 {%0,%1,%2,%3}, [%4];"
                 : "=r"(r0), "=r"(r1), "=r"(r2), "=r"(r3) : "r"(addr));
}
__device__ __forceinline__ void mma16816(float* c, const uint32_t* a, uint32_t b0, uint32_t b1) {
    asm volatile(
        "mma.sync.aligned.m16n8k16.row.col.f32.bf16.bf16.f32 "
        "{%0,%1,%2,%3}, {%4,%5,%6,%7}, {%8,%9}, {%0,%1,%2,%3};"
        : "+f"(c[0]), "+f"(c[1]), "+f"(c[2]), "+f"(c[3])
        : "r"(a[0]), "r"(a[1]), "r"(a[2]), "r"(a[3]), "r"(b0), "r"(b1));
}

// ============================================================
// Prep 1: traces + bf16(pre_spikes) + trace-nonzero detection
// ============================================================
__global__ void prep_ew(const float4* __restrict__ pre_sp,
                        const float4* __restrict__ pre_tr,
                        const float4* __restrict__ post_sp,
                        const float4* __restrict__ post_tr,
                        float4* __restrict__ new_pre,
                        float4* __restrict__ new_post,
                        uint2* __restrict__ preb,
                        long long n_pre4, long long n_post4)
{
    long long total = n_pre4 + n_post4;
    int nz = 0;
    for (long long i = (long long)blockIdx.x * blockDim.x + threadIdx.x;
         i < total; i += (long long)gridDim.x * blockDim.x) {
        if (i < n_pre4) {
            float4 s = pre_sp[i], t = pre_tr[i];
            if (t.x != 0.f || t.y != 0.f || t.z != 0.f || t.w != 0.f) nz |= 1;
            float4 o;
            o.x = t.x * DECAYF + s.x; o.y = t.y * DECAYF + s.y;
            o.z = t.z * DECAYF + s.z; o.w = t.w * DECAYF + s.w;
            new_pre[i] = o;
            __nv_bfloat162 b0 = __float22bfloat162_rn(make_float2(s.x, s.y));
            __nv_bfloat162 b1 = __float22bfloat162_rn(make_float2(s.z, s.w));
            union { __nv_bfloat162 h[2]; uint2 u; } cv; cv.h[0] = b0; cv.h[1] = b1;
            preb[i] = cv.u;
        } else {
            long long j = i - n_pre4;
            float4 s = post_sp[j], t = post_tr[j];
            if (t.x != 0.f || t.y != 0.f || t.z != 0.f || t.w != 0.f) nz |= 2;
            float4 o;
            o.x = t.x * DECAYF + s.x; o.y = t.y * DECAYF + s.y;
            o.z = t.z * DECAYF + s.z; o.w = t.w * DECAYF + s.w;
            new_post[j] = o;
        }
    }
    unsigned m1 = __ballot_sync(0xffffffffu, nz & 1);
    unsigned m2 = __ballot_sync(0xffffffffu, nz & 2);
    if ((threadIdx.x & 31) == 0) {
        int v = (m1 ? 1 : 0) | (m2 ? 2 : 0);
        if (v) atomicOr(&g_trace_nz, v);
    }
}

// ============================================================
// Prep 2: transpose + scale + bf16, 4 slices via internal z loop
// ============================================================
__global__ void __launch_bounds__(256)
prep_tr4(const float* __restrict__ x0, const float* __restrict__ x1,
         const float* __restrict__ x2, const float* __restrict__ x3,
         __nv_bfloat16* __restrict__ yA, __nv_bfloat16* __restrict__ yB,
         float s0, float s1)
{
    if (g_trace_nz == 0) return;
    __shared__ float tf[64][65];
    const int m0 = blockIdx.x << 6;
    const int k0 = blockIdx.y << 6;
    const int tid = threadIdx.x;
    #pragma unroll 1
    for (int z = 0; z < 4; ++z) {
        const float* X = (z == 0) ? x0 : (z == 1) ? x1 : (z == 2) ? x2 : x3;
        __nv_bfloat16* Y = (z < 2) ? yA : yB;
        const float scale = (z == 0) ? s0 : (z == 1) ? s1 : 1.0f;
        const int koff = (z & 1) ? BB : 0;
        #pragma unroll
        for (int i = 0; i < 4; ++i) {
            int flat = tid + (i << 8);
            int kr = flat >> 4;
            int mc = (flat & 15) << 2;
            float4 v = *(const float4*)(X + (size_t)(k0 + kr) * 4096 + m0 + mc);
            tf[kr][mc + 0] = v.x; tf[kr][mc + 1] = v.y;
            tf[kr][mc + 2] = v.z; tf[kr][mc + 3] = v.w;
        }
        __syncthreads();
        int m = tid >> 2;
        int seg = (tid & 3) << 4;
        __align__(16) __nv_bfloat16 buf[16];
        #pragma unroll
        for (int j = 0; j < 16; ++j)
            buf[j] = __float2bfloat16(tf[seg + j][m] * scale);
        __nv_bfloat16* dst = Y + (size_t)(m0 + m) * K1 + koff + k0 + seg;
        *(uint4*)(dst)     = *(uint4*)&buf[0];
        *(uint4*)(dst + 8) = *(uint4*)&buf[8];
        __syncthreads();
    }
}

// ============================================================
// Weight update (combined): dispatches on g_trace_nz.
// flag==0 -> elementwise clip(W + dh) with batched loads.
// flag!=0 -> TN GEMM K=2048 + fused epilogue.
// ============================================================
__global__ void __launch_bounds__(256, 2)
wupdate_mma(const __nv_bfloat16* __restrict__ A,
            const __nv_bfloat16* __restrict__ Bmat,
            const float* __restrict__ W,
            const float* __restrict__ rr,
            float* __restrict__ Out,
            __nv_bfloat16* __restrict__ OutB,
            int Ktot, int Nld)
{
    const int tid = threadIdx.x;
    const int bm = blockIdx.y << 7;
    const int bn = blockIdx.x << 7;

    if (g_trace_nz == 0) {
        #pragma unroll 1
        for (int b2 = 0; b2 < 4; ++b2) {
            float4 wv[4];
            float  dhv[4];
            size_t ov[4];
            #pragma unroll
            for (int u = 0; u < 4; ++u) {
                int flat = tid + ((b2 * 4 + u) << 8);
                int row  = flat >> 5;
                int c4   = (flat & 31) << 2;
                int gp   = bm + row;
                ov[u]  = (size_t)gp * PREN + bn + c4;
                dhv[u] = -HOMEO * (rr[gp] - TARGET_RATE);
                wv[u]  = *(const float4*)(W + ov[u]);
            }
            #pragma unroll
            for (int u = 0; u < 4; ++u) {
                float4 w = wv[u];
                float dh = dhv[u];
                w.x = fminf(fmaxf(w.x + dh, W_MINV), W_MAXV);
                w.y = fminf(fmaxf(w.y + dh, W_MINV), W_MAXV);
                w.z = fminf(fmaxf(w.z + dh, W_MINV), W_MAXV);
                w.w = fminf(fmaxf(w.w + dh, W_MINV), W_MAXV);
                *(float4*)(Out + ov[u]) = w;
                __nv_bfloat162 b0 = __float22bfloat162_rn(make_float2(w.x, w.y));
                __nv_bfloat162 b1 = __float22bfloat162_rn(make_float2(w.z, w.w));
                union { __nv_bfloat162 h[2]; uint2 u2; } cv; cv.h[0] = b0; cv.h[1] = b1;
                *(uint2*)(OutB + ov[u]) = cv.u2;
            }
        }
        return;
    }

    extern __shared__ char smraw[];
    const uint32_t sbase = smem_u32(smraw);
    const int wid  = tid >> 5;
    const int lane = tid & 31;
    const int wm = (wid & 1) << 6;
    const int wn = (wid >> 1) << 5;

    uint32_t st_off[2];
    int g_row[2], g_col[2];
    #pragma unroll
    for (int i = 0; i < 2; ++i) {
        int flat = tid + (i << 8);
        int row = flat >> 2, ch = flat & 3;
        int sw = ch ^ ((row >> 1) & 3);
        st_off[i] = (uint32_t)(row * 64 + sw * 16);
        g_row[i] = row; g_col[i] = ch * 8;
    }

    const int grp = lane >> 3, rowin = lane & 7;
    uint32_t offA[2][4], offB[2][2];
    #pragma unroll
    for (int kk = 0; kk < 2; ++kk) {
        #pragma unroll
        for (int i = 0; i < 4; ++i) {
            int row = wm + i * 16 + ((grp & 1) << 3) + rowin;
            int ch  = (kk << 1) + (grp >> 1);
            int sw  = ch ^ ((row >> 1) & 3);
            offA[kk][i] = (uint32_t)(row * 64 + sw * 16);
        }
        #pragma unroll
        for (int jp = 0; jp < 2; ++jp) {
            int row = wn + jp * 16 + ((grp >> 1) << 3) + rowin;
            int ch  = (kk << 1) + (grp & 1);
            int sw  = ch ^ ((row >> 1) & 3);
            offB[kk][jp] = (uint32_t)(8192 + row * 64 + sw * 16);
        }
    }

    const __nv_bfloat16* Ag = A    + (size_t)bm * Ktot;
    const __nv_bfloat16* Bg = Bmat + (size_t)bn * Ktot;

    float acc[4][4][4];
    #pragma unroll
    for (int i = 0; i < 4; ++i)
        #pragma unroll
        for (int j = 0; j < 4; ++j)
            #pragma unroll
            for (int r = 0; r < 4; ++r) acc[i][j][r] = 0.f;

    const int NK = Ktot >> 5;

    #pragma unroll
    for (int s = 0; s < 3; ++s) {
        uint32_t sb = sbase + (uint32_t)s * 16384u;
        int k0 = s << 5;
        #pragma unroll
        for (int i = 0; i < 2; ++i) {
            const void* pa = Ag + (size_t)g_row[i] * Ktot + k0 + g_col[i];
            asm volatile("cp.async.cg.shared.global [%0], [%1], 16;" :: "r"(sb + st_off[i]), "l"(pa));
        }
        #pragma unroll
        for (int i = 0; i < 2; ++i) {
            const void* pb = Bg + (size_t)g_row[i] * Ktot + k0 + g_col[i];
            asm volatile("cp.async.cg.shared.global [%0], [%1], 16;" :: "r"(sb + 8192u + st_off[i]), "l"(pb));
        }
        asm volatile("cp.async.commit_group;" ::: "memory");
    }

    for (int it = 0; it < NK; ++it) {
        const int s = it & 3;
        if (it < NK - 2)       asm volatile("cp.async.wait_group 2;" ::: "memory");
        else if (it == NK - 2) asm volatile("cp.async.wait_group 1;" ::: "memory");
        else                   asm volatile("cp.async.wait_group 0;" ::: "memory");
        __syncthreads();

        if (it + 3 < NK) {
            uint32_t sb2 = sbase + (uint32_t)((it + 3) & 3) * 16384u;
            int k0 = (it + 3) << 5;
            #pragma unroll
            for (int i = 0; i < 2; ++i) {
                const void* pa = Ag + (size_t)g_row[i] * Ktot + k0 + g_col[i];
                asm volatile("cp.async.cg.shared.global [%0], [%1], 16;" :: "r"(sb2 + st_off[i]), "l"(pa));
            }
            #pragma unroll
            for (int i = 0; i < 2; ++i) {
                const void* pb = Bg + (size_t)g_row[i] * Ktot + k0 + g_col[i];
                asm volatile("cp.async.cg.shared.global [%0], [%1], 16;" :: "r"(sb2 + 8192u + st_off[i]), "l"(pb));
            }
            asm volatile("cp.async.commit_group;" ::: "memory");
        }

        const uint32_t sb = sbase + (uint32_t)s * 16384u;
        #pragma unroll
        for (int kk = 0; kk < 2; ++kk) {
            uint32_t a[4][4], b[2][4];
            #pragma unroll
            for (int i = 0; i < 4; ++i)
                ldsm4(a[i][0], a[i][1], a[i][2], a[i][3], sb + offA[kk][i]);
            #pragma unroll
            for (int jp = 0; jp < 2; ++jp)
                ldsm4(b[jp][0], b[jp][1], b[jp][2], b[jp][3], sb + offB[kk][jp]);
            #pragma unroll
            for (int i = 0; i < 4; ++i)
                #pragma unroll
                for (int j = 0; j < 4; ++j)
                    mma16816(acc[i][j], a[i], b[j >> 1][(j & 1) * 2 + 0], b[j >> 1][(j & 1) * 2 + 1]);
        }
    }

    const int qid = lane >> 2;
    const int ql  = (lane & 3) << 1;
    #pragma unroll
    for (int i = 0; i < 4; ++i) {
        const int gp0 = bm + wm + i * 16 + qid;
        float dh0 = -HOMEO * (rr[gp0]     - TARGET_RATE);
        float dh1 = -HOMEO * (rr[gp0 + 8] - TARGET_RATE);
        #pragma unroll
        for (int j = 0; j < 4; ++j) {
            const int gq = bn + wn + j * 8 + ql;
            const size_t o0 = (size_t)gp0 * Nld + gq;
            const size_t o1 = o0 + (size_t)8 * Nld;
            float2 w0 = *(const float2*)(W + o0);
            float2 w1 = *(const float2*)(W + o1);
            float x0 = fminf(fmaxf(w0.x + acc[i][j][0] + dh0, W_MINV), W_MAXV);
            float x1 = fminf(fmaxf(w0.y + acc[i][j][1] + dh0, W_MINV), W_MAXV);
            float y0 = fminf(fmaxf(w1.x + acc[i][j][2] + dh1, W_MINV), W_MAXV);
            float y1 = fminf(fmaxf(w1.y + acc[i][j][3] + dh1, W_MINV), W_MAXV);
            *(float2*)(Out + o0) = make_float2(x0, x1);
            *(float2*)(Out + o1) = make_float2(y0, y1);
            union { __nv_bfloat162 h; uint32_t u; } c0, c1;
            c0.h = __float22bfloat162_rn(make_float2(x0, x1));
            c1.h = __float22bfloat162_rn(make_float2(y0, y1));
            *(uint32_t*)(OutB + o0) = c0.u;
            *(uint32_t*)(OutB + o1) = c1.u;
        }
    }
}

// ============================================================
// GEMM2 (current): 128x128 tile, BK=64, 3-stage pipeline,
// 8 warps, 96KB smem, 2 CTAs/SM.  Resets g_trace_nz.
// ============================================================
__global__ void __launch_bounds__(256, 2)
gemm2_mma(const __nv_bfloat16* __restrict__ A,
          const __nv_bfloat16* __restrict__ Bmat,
          float* __restrict__ Out,
          int Ktot, int Nld)
{
    const int tid = threadIdx.x;
    if (tid == 0 && blockIdx.x == 0 && blockIdx.y == 0) g_trace_nz = 0;

    extern __shared__ char smraw[];
    const uint32_t sbase = smem_u32(smraw);
    const int wid  = tid >> 5;
    const int lane = tid & 31;
    const int bm = blockIdx.y << 7;
    const int bn = blockIdx.x << 7;
    const int wm = (wid & 1) << 6;
    const int wn = (wid >> 1) << 5;

    uint32_t st[4];
    int gr[4], gc[4];
    #pragma unroll
    for (int i = 0; i < 4; ++i) {
        int flat = tid + (i << 8);
        int row = flat >> 3, ch = flat & 7;
        int sw = ch ^ (row & 7);
        st[i] = (uint32_t)(row * 128 + sw * 16);
        gr[i] = row; gc[i] = ch * 8;
    }

    const int grp = lane >> 3, rowin = lane & 7;
    uint32_t offA[2][4], offB[2][2];
    #pragma unroll
    for (int kk = 0; kk < 2; ++kk) {
        #pragma unroll
        for (int i = 0; i < 4; ++i) {
            int row = wm + i * 16 + ((grp & 1) << 3) + rowin;
            int ch  = (kk << 1) + (grp >> 1);
            int sw  = ch ^ (row & 7);
            offA[kk][i] = (uint32_t)(row * 128 + sw * 16);
        }
        #pragma unroll
        for (int jp = 0; jp < 2; ++jp) {
            int row = wn + jp * 16 + ((grp >> 1) << 3) + rowin;
            int ch  = (kk << 1) + (grp & 1);
            int sw  = ch ^ (row & 7);
            offB[kk][jp] = (uint32_t)(16384 + row * 128 + sw * 16);
        }
    }

    const __nv_bfloat16* Ag = A    + (size_t)bm * Ktot;
    const __nv_bfloat16* Bg = Bmat + (size_t)bn * Ktot;

    float acc[4][4][4];
    #pragma unroll
    for (int i = 0; i < 4; ++i)
        #pragma unroll
        for (int j = 0; j < 4; ++j)
            #pragma unroll
            for (int r = 0; r < 4; ++r) acc[i][j][r] = 0.f;

    const int NK = Ktot >> 6;
    const uint32_t SST = 32768u;

    #pragma unroll
    for (int s = 0; s < 2; ++s) {
        uint32_t sb = sbase + (uint32_t)s * SST;
        int k0 = s << 6;
        #pragma unroll
        for (int i = 0; i < 4; ++i) {
            const void* pa = Ag + (size_t)gr[i] * Ktot + k0 + gc[i];
            asm volatile("cp.async.cg.shared.global [%0], [%1], 16;" :: "r"(sb + st[i]), "l"(pa));
            const void* pb = Bg + (size_t)gr[i] * Ktot + k0 + gc[i];
            asm volatile("cp.async.cg.shared.global [%0], [%1], 16;" :: "r"(sb + 16384u + st[i]), "l"(pb));
        }
        asm volatile("cp.async.commit_group;" ::: "memory");
    }

    for (int it = 0; it < NK; ++it) {
        if (it < NK - 1) asm volatile("cp.async.wait_group 1;" ::: "memory");
        else             asm volatile("cp.async.wait_group 0;" ::: "memory");
        __syncthreads();

        if (it + 2 < NK) {
            uint32_t sb2 = sbase + (uint32_t)((it + 2) % 3) * SST;
            int k0 = (it + 2) << 6;
            #pragma unroll
            for (int i = 0; i < 4; ++i) {
                const void* pa = Ag + (size_t)gr[i] * Ktot + k0 + gc[i];
                asm volatile("cp.async.cg.shared.global [%0], [%1], 16;" :: "r"(sb2 + st[i]), "l"(pa));
                const void* pb = Bg + (size_t)gr[i] * Ktot + k0 + gc[i];
                asm volatile("cp.async.cg.shared.global [%0], [%1], 16;" :: "r"(sb2 + 16384u + st[i]), "l"(pb));
            }
            asm volatile("cp.async.commit_group;" ::: "memory");
        }

        const uint32_t sb = sbase + (uint32_t)(it % 3) * SST;
        #pragma unroll
        for (int kk = 0; kk < 4; ++kk) {
            const uint32_t xm = (kk & 2) ? 64u : 0u;
            const int ki = kk & 1;
            uint32_t a[4][4], b[2][4];
            #pragma unroll
            for (int i = 0; i < 4; ++i)
                ldsm4(a[i][0], a[i][1], a[i][2], a[i][3], sb + (offA[ki][i] ^ xm));
            #pragma unroll
            for (int jp = 0; jp < 2; ++jp)
                ldsm4(b[jp][0], b[jp][1], b[jp][2], b[jp][3], sb + (offB[ki][jp] ^ xm));
            #pragma unroll
            for (int i = 0; i < 4; ++i)
                #pragma unroll
                for (int j = 0; j < 4; ++j)
                    mma16816(acc[i][j], a[i], b[j >> 1][(j & 1) * 2 + 0], b[j >> 1][(j & 1) * 2 + 1]);
        }
    }

    const int qid = lane >> 2;
    const int ql  = (lane & 3) << 1;
    #pragma unroll
    for (int i = 0; i < 4; ++i) {
        const int gp0 = bm + wm + i * 16 + qid;
        #pragma unroll
        for (int j = 0; j < 4; ++j) {
            const int gq = bn + wn + j * 8 + ql;
            const size_t o0 = (size_t)gp0 * Nld + gq;
            const size_t o1 = o0 + (size_t)8 * Nld;
            *(float2*)(Out + o0) = make_float2(acc[i][j][0], acc[i][j][1]);
            *(float2*)(Out + o1) = make_float2(acc[i][j][2], acc[i][j][3]);
        }
    }
}

// ============================================================
// Rate partials (after gemm2; independent of flag) + EMA tail.
// ============================================================
__global__ void __launch_bounds__(256)
rate_partial_kernel(const float* __restrict__ post_sp)
{
    const int c4  = blockIdx.x * 256 + threadIdx.x;
    const int chunk = blockIdx.y;
    const int rows = BB / RATE_CHUNKS;                  // 32
    const float4* base = (const float4*)(post_sp) + (size_t)chunk * rows * (POSTN / 4) + c4;
    float4 a0 = make_float4(0.f, 0.f, 0.f, 0.f);
    float4 a1 = make_float4(0.f, 0.f, 0.f, 0.f);
    #pragma unroll
    for (int r = 0; r < rows; r += 2) {
        float4 v0 = base[(size_t)r * (POSTN / 4)];
        float4 v1 = base[(size_t)(r + 1) * (POSTN / 4)];
        a0.x += v0.x; a0.y += v0.y; a0.z += v0.z; a0.w += v0.w;
        a1.x += v1.x; a1.y += v1.y; a1.z += v1.z; a1.w += v1.w;
    }
    float4 s;
    s.x = a0.x + a1.x; s.y = a0.y + a1.y; s.z = a0.z + a1.z; s.w = a0.w + a1.w;
    *((float4*)g_rate_partial + (size_t)chunk * (POSTN / 4) + c4) = s;
}

__global__ void __launch_bounds__(256)
rate_ema_kernel(const float* __restrict__ rr, float* __restrict__ new_rate)
{
    const int c4 = blockIdx.x * 256 + threadIdx.x;      // float4 column, 0..1023
    float4 s = make_float4(0.f, 0.f, 0.f, 0.f);
    #pragma unroll
    for (int c = 0; c < RATE_CHUNKS; ++c) {
        float4 v = *((const float4*)g_rate_partial + (size_t)c * (POSTN / 4) + c4);
        s.x += v.x; s.y += v.y; s.z += v.z; s.w += v.w;
    }
    float4 r = *((const float4*)rr + c4);
    float4 o;
    o.x = r.x * (1.0f - RATE_ALPHA) + RATE_ALPHA * (s.x / (float)BB);
    o.y = r.y * (1.0f - RATE_ALPHA) + RATE_ALPHA * (s.y / (float)BB);
    o.z = r.z * (1.0f - RATE_ALPHA) + RATE_ALPHA * (s.z / (float)BB);
    o.w = r.w * (1.0f - RATE_ALPHA) + RATE_ALPHA * (s.w / (float)BB);
    *((float4*)new_rate + c4) = o;
}

// ============================================================
// launch
// ============================================================
extern "C" void kernel_launch(void* const* d_in, const int* in_sizes, int n_in,
                              void* d_out, int out_size)
{
    const float* pre_sp  = (const float*)d_in[0];
    const float* post_sp = (const float*)d_in[1];
    const float* W       = (const float*)d_in[2];
    const float* pre_tr  = (const float*)d_in[3];
    const float* post_tr = (const float*)d_in[4];
    const float* rr      = (const float*)d_in[5];

    float* out = (float*)d_out;
    float* cur      = out;
    float* wn       = cur + (size_t)BB * POSTN;
    float* new_pre  = wn + (size_t)POSTN * PREN;
    float* new_post = new_pre + (size_t)BB * PREN;
    float* new_rate = new_post + (size_t)BB * POSTN;

    void *pA, *pB, *pPre, *pWb;
    cudaGetSymbolAddress(&pA,   g_A);
    cudaGetSymbolAddress(&pB,   g_Bm);
    cudaGetSymbolAddress(&pPre, g_preb);
    cudaGetSymbolAddress(&pWb,  g_Wb);

    const int SMEM1 = 4 * 16384;   // 64KB (wupdate GEMM path)
    const int SMEM2 = 3 * 32768;   // 96KB (gemm2, 3-stage BK=64)
    cudaFuncSetAttribute(wupdate_mma, cudaFuncAttributeMaxDynamicSharedMemorySize, SMEM1);
    cudaFuncSetAttribute(gemm2_mma,   cudaFuncAttributeMaxDynamicSharedMemorySize, SMEM2);

    // launch 0: traces + bf16(pre_spikes) + flag detection
    {
        long long n_pre4  = (long long)BB * PREN / 4;
        long long n_post4 = (long long)BB * POSTN / 4;
        prep_ew<<<2048, 256>>>((const float4*)pre_sp, (const float4*)pre_tr,
                               (const float4*)post_sp, (const float4*)post_tr,
                               (float4*)new_pre, (float4*)new_post,
                               (uint2*)pPre, n_pre4, n_post4);
    }

    // launch 1: K-major bf16 transposes (self-gated)
    {
        const float S0 = (A_PLUS * DECAYF) / (float)BB;
        const float S1 = -(A_MINUS * DECAYF) / (float)BB;
        dim3 g(4096 / 64, BB / 64);
        prep_tr4<<<g, 256>>>(post_sp, post_tr, pre_tr, pre_sp,
                             (__nv_bfloat16*)pA, (__nv_bfloat16*)pB, S0, S1);
    }

    // launch 2: weight update (combined fast/GEMM dispatch)
    {
        dim3 grid(PREN / 128, POSTN / 128);
        wupdate_mma<<<grid, 256, SMEM1>>>((const __nv_bfloat16*)pA,
                                          (const __nv_bfloat16*)pB,
                                          W, rr, wn, (__nv_bfloat16*)pWb, K1, PREN);
    }

    // launch 3 (profiled slot): current = pre_spikes @ new_weights^T + flag reset
    {
        dim3 grid(POSTN / 128, BB / 128);
        gemm2_mma<<<grid, 256, SMEM2>>>((const __nv_bfloat16*)pPre,
                                        (const __nv_bfloat16*)pWb,
                                        cur, PREN, POSTN);
    }

    // launches 4,5: rate partials + EMA (independent of the above)
    {
        dim3 g1(POSTN / 1024, RATE_CHUNKS);
        rate_partial_kernel<<<g1, 256>>>(post_sp);
        rate_ema_kernel<<<POSTN / 1024, 256>>>(rr, new_rate);
    }
}

// round 12
// speedup vs baseline: 1.0177x; 1.0177x over previous
#include <cuda_runtime.h>
#include <cuda_bf16.h>
#include <cstdint>

// ---------------- STDP constants ----------------
#define A_PLUS      0.01f
#define A_MINUS     0.01f
#define W_MAXV      1.0f
#define W_MINV      0.0f
#define TARGET_RATE 0.1f
#define HOMEO       0.001f
#define RATE_ALPHA  0.01f
#define DECAYF      0.9512294245007140f   // exp(-1/20)

// ---------------- fixed shapes ----------------
#define BB    1024
#define PREN  4096
#define POSTN 4096
#define K1    2048
#define RATE_CHUNKS 32

// ---------------- device scratch ----------------
__device__ __align__(128) __nv_bfloat16 g_A   [(size_t)POSTN * K1];
__device__ __align__(128) __nv_bfloat16 g_Bm  [(size_t)PREN  * K1];
__device__ __align__(128) __nv_bfloat16 g_preb[(size_t)BB    * PREN];
__device__ __align__(128) __nv_bfloat16 g_Wb  [(size_t)POSTN * PREN];
__device__ float g_rate_partial[RATE_CHUNKS * POSTN];
__device__ int   g_trace_nz;   // set by prep_ew; reset by gemm2

// ============================================================
// asm helpers
// ============================================================
__device__ __forceinline__ uint32_t smem_u32(const void* p) {
    uint32_t a;
    asm("{ .reg .u64 t; cvta.to.shared.u64 t, %1; cvt.u32.u64 %0, t; }" : "=r"(a) : "l"(p));
    return a;
}
__device__ __forceinline__ void ldsm4(uint32_t& r0, uint32_t& r1, uint32_t& r2, uint32_t& r3,
                                      uint32_t addr) {
    asm volatile("ldmatrix.sync.aligned.m8n8.x4.shared.b16 {%0,%1,%2,%3}, [%4];"
                 : "=r"(r0), "=r"(r1), "=r"(r2), "=r"(r3) : "r"(addr));
}
__device__ __forceinline__ void mma16816(float* c, const uint32_t* a, uint32_t b0, uint32_t b1) {
    asm volatile(
        "mma.sync.aligned.m16n8k16.row.col.f32.bf16.bf16.f32 "
        "{%0,%1,%2,%3}, {%4,%5,%6,%7}, {%8,%9}, {%0,%1,%2,%3};"
        : "+f"(c[0]), "+f"(c[1]), "+f"(c[2]), "+f"(c[3])
        : "r"(a[0]), "r"(a[1]), "r"(a[2]), "r"(a[3]), "r"(b0), "r"(b1));
}

// ============================================================
// Prep 1: traces + bf16(pre_spikes) + trace-nonzero detection
// ============================================================
__global__ void prep_ew(const float4* __restrict__ pre_sp,
                        const float4* __restrict__ pre_tr,
                        const float4* __restrict__ post_sp,
                        const float4* __restrict__ post_tr,
                        float4* __restrict__ new_pre,
                        float4* __restrict__ new_post,
                        uint2* __restrict__ preb,
                        long long n_pre4, long long n_post4)
{
    long long total = n_pre4 + n_post4;
    int nz = 0;
    for (long long i = (long long)blockIdx.x * blockDim.x + threadIdx.x;
         i < total; i += (long long)gridDim.x * blockDim.x) {
        if (i < n_pre4) {
            float4 s = pre_sp[i], t = pre_tr[i];
            if (t.x != 0.f || t.y != 0.f || t.z != 0.f || t.w != 0.f) nz |= 1;
            float4 o;
            o.x = t.x * DECAYF + s.x; o.y = t.y * DECAYF + s.y;
            o.z = t.z * DECAYF + s.z; o.w = t.w * DECAYF + s.w;
            new_pre[i] = o;
            __nv_bfloat162 b0 = __float22bfloat162_rn(make_float2(s.x, s.y));
            __nv_bfloat162 b1 = __float22bfloat162_rn(make_float2(s.z, s.w));
            union { __nv_bfloat162 h[2]; uint2 u; } cv; cv.h[0] = b0; cv.h[1] = b1;
            preb[i] = cv.u;
        } else {
            long long j = i - n_pre4;
            float4 s = post_sp[j], t = post_tr[j];
            if (t.x != 0.f || t.y != 0.f || t.z != 0.f || t.w != 0.f) nz |= 2;
            float4 o;
            o.x = t.x * DECAYF + s.x; o.y = t.y * DECAYF + s.y;
            o.z = t.z * DECAYF + s.z; o.w = t.w * DECAYF + s.w;
            new_post[j] = o;
        }
    }
    unsigned m1 = __ballot_sync(0xffffffffu, nz & 1);
    unsigned m2 = __ballot_sync(0xffffffffu, nz & 2);
    if ((threadIdx.x & 31) == 0) {
        int v = (m1 ? 1 : 0) | (m2 ? 2 : 0);
        if (v) atomicOr(&g_trace_nz, v);
    }
}

// ============================================================
// Prep 2: transpose + scale + bf16, 4 slices via internal z loop
// ============================================================
__global__ void __launch_bounds__(256)
prep_tr4(const float* __restrict__ x0, const float* __restrict__ x1,
         const float* __restrict__ x2, const float* __restrict__ x3,
         __nv_bfloat16* __restrict__ yA, __nv_bfloat16* __restrict__ yB,
         float s0, float s1)
{
    if (g_trace_nz == 0) return;
    __shared__ float tf[64][65];
    const int m0 = blockIdx.x << 6;
    const int k0 = blockIdx.y << 6;
    const int tid = threadIdx.x;
    #pragma unroll 1
    for (int z = 0; z < 4; ++z) {
        const float* X = (z == 0) ? x0 : (z == 1) ? x1 : (z == 2) ? x2 : x3;
        __nv_bfloat16* Y = (z < 2) ? yA : yB;
        const float scale = (z == 0) ? s0 : (z == 1) ? s1 : 1.0f;
        const int koff = (z & 1) ? BB : 0;
        #pragma unroll
        for (int i = 0; i < 4; ++i) {
            int flat = tid + (i << 8);
            int kr = flat >> 4;
            int mc = (flat & 15) << 2;
            float4 v = *(const float4*)(X + (size_t)(k0 + kr) * 4096 + m0 + mc);
            tf[kr][mc + 0] = v.x; tf[kr][mc + 1] = v.y;
            tf[kr][mc + 2] = v.z; tf[kr][mc + 3] = v.w;
        }
        __syncthreads();
        int m = tid >> 2;
        int seg = (tid & 3) << 4;
        __align__(16) __nv_bfloat16 buf[16];
        #pragma unroll
        for (int j = 0; j < 16; ++j)
            buf[j] = __float2bfloat16(tf[seg + j][m] * scale);
        __nv_bfloat16* dst = Y + (size_t)(m0 + m) * K1 + koff + k0 + seg;
        *(uint4*)(dst)     = *(uint4*)&buf[0];
        *(uint4*)(dst + 8) = *(uint4*)&buf[8];
        __syncthreads();
    }
}

// ============================================================
// Weight update (combined): dispatches on g_trace_nz.
// ============================================================
__global__ void __launch_bounds__(256, 2)
wupdate_mma(const __nv_bfloat16* __restrict__ A,
            const __nv_bfloat16* __restrict__ Bmat,
            const float* __restrict__ W,
            const float* __restrict__ rr,
            float* __restrict__ Out,
            __nv_bfloat16* __restrict__ OutB,
            int Ktot, int Nld)
{
    const int tid = threadIdx.x;
    const int bm = blockIdx.y << 7;
    const int bn = blockIdx.x << 7;

    if (g_trace_nz == 0) {
        #pragma unroll 1
        for (int b2 = 0; b2 < 4; ++b2) {
            float4 wv[4];
            float  dhv[4];
            size_t ov[4];
            #pragma unroll
            for (int u = 0; u < 4; ++u) {
                int flat = tid + ((b2 * 4 + u) << 8);
                int row  = flat >> 5;
                int c4   = (flat & 31) << 2;
                int gp   = bm + row;
                ov[u]  = (size_t)gp * PREN + bn + c4;
                dhv[u] = -HOMEO * (rr[gp] - TARGET_RATE);
                wv[u]  = *(const float4*)(W + ov[u]);
            }
            #pragma unroll
            for (int u = 0; u < 4; ++u) {
                float4 w = wv[u];
                float dh = dhv[u];
                w.x = fminf(fmaxf(w.x + dh, W_MINV), W_MAXV);
                w.y = fminf(fmaxf(w.y + dh, W_MINV), W_MAXV);
                w.z = fminf(fmaxf(w.z + dh, W_MINV), W_MAXV);
                w.w = fminf(fmaxf(w.w + dh, W_MINV), W_MAXV);
                *(float4*)(Out + ov[u]) = w;
                __nv_bfloat162 b0 = __float22bfloat162_rn(make_float2(w.x, w.y));
                __nv_bfloat162 b1 = __float22bfloat162_rn(make_float2(w.z, w.w));
                union { __nv_bfloat162 h[2]; uint2 u2; } cv; cv.h[0] = b0; cv.h[1] = b1;
                *(uint2*)(OutB + ov[u]) = cv.u2;
            }
        }
        return;
    }

    extern __shared__ char smraw[];
    const uint32_t sbase = smem_u32(smraw);
    const int wid  = tid >> 5;
    const int lane = tid & 31;
    const int wm = (wid & 1) << 6;
    const int wn = (wid >> 1) << 5;

    uint32_t st_off[2];
    int g_row[2], g_col[2];
    #pragma unroll
    for (int i = 0; i < 2; ++i) {
        int flat = tid + (i << 8);
        int row = flat >> 2, ch = flat & 3;
        int sw = ch ^ ((row >> 1) & 3);
        st_off[i] = (uint32_t)(row * 64 + sw * 16);
        g_row[i] = row; g_col[i] = ch * 8;
    }

    const int grp = lane >> 3, rowin = lane & 7;
    uint32_t offA[2][4], offB[2][2];
    #pragma unroll
    for (int kk = 0; kk < 2; ++kk) {
        #pragma unroll
        for (int i = 0; i < 4; ++i) {
            int row = wm + i * 16 + ((grp & 1) << 3) + rowin;
            int ch  = (kk << 1) + (grp >> 1);
            int sw  = ch ^ ((row >> 1) & 3);
            offA[kk][i] = (uint32_t)(row * 64 + sw * 16);
        }
        #pragma unroll
        for (int jp = 0; jp < 2; ++jp) {
            int row = wn + jp * 16 + ((grp >> 1) << 3) + rowin;
            int ch  = (kk << 1) + (grp & 1);
            int sw  = ch ^ ((row >> 1) & 3);
            offB[kk][jp] = (uint32_t)(8192 + row * 64 + sw * 16);
        }
    }

    const __nv_bfloat16* Ag = A    + (size_t)bm * Ktot;
    const __nv_bfloat16* Bg = Bmat + (size_t)bn * Ktot;

    float acc[4][4][4];
    #pragma unroll
    for (int i = 0; i < 4; ++i)
        #pragma unroll
        for (int j = 0; j < 4; ++j)
            #pragma unroll
            for (int r = 0; r < 4; ++r) acc[i][j][r] = 0.f;

    const int NK = Ktot >> 5;

    #pragma unroll
    for (int s = 0; s < 3; ++s) {
        uint32_t sb = sbase + (uint32_t)s * 16384u;
        int k0 = s << 5;
        #pragma unroll
        for (int i = 0; i < 2; ++i) {
            const void* pa = Ag + (size_t)g_row[i] * Ktot + k0 + g_col[i];
            asm volatile("cp.async.cg.shared.global [%0], [%1], 16;" :: "r"(sb + st_off[i]), "l"(pa));
        }
        #pragma unroll
        for (int i = 0; i < 2; ++i) {
            const void* pb = Bg + (size_t)g_row[i] * Ktot + k0 + g_col[i];
            asm volatile("cp.async.cg.shared.global [%0], [%1], 16;" :: "r"(sb + 8192u + st_off[i]), "l"(pb));
        }
        asm volatile("cp.async.commit_group;" ::: "memory");
    }

    for (int it = 0; it < NK; ++it) {
        const int s = it & 3;
        if (it < NK - 2)       asm volatile("cp.async.wait_group 2;" ::: "memory");
        else if (it == NK - 2) asm volatile("cp.async.wait_group 1;" ::: "memory");
        else                   asm volatile("cp.async.wait_group 0;" ::: "memory");
        __syncthreads();

        if (it + 3 < NK) {
            uint32_t sb2 = sbase + (uint32_t)((it + 3) & 3) * 16384u;
            int k0 = (it + 3) << 5;
            #pragma unroll
            for (int i = 0; i < 2; ++i) {
                const void* pa = Ag + (size_t)g_row[i] * Ktot + k0 + g_col[i];
                asm volatile("cp.async.cg.shared.global [%0], [%1], 16;" :: "r"(sb2 + st_off[i]), "l"(pa));
            }
            #pragma unroll
            for (int i = 0; i < 2; ++i) {
                const void* pb = Bg + (size_t)g_row[i] * Ktot + k0 + g_col[i];
                asm volatile("cp.async.cg.shared.global [%0], [%1], 16;" :: "r"(sb2 + 8192u + st_off[i]), "l"(pb));
            }
            asm volatile("cp.async.commit_group;" ::: "memory");
        }

        const uint32_t sb = sbase + (uint32_t)s * 16384u;
        #pragma unroll
        for (int kk = 0; kk < 2; ++kk) {
            uint32_t a[4][4], b[2][4];
            #pragma unroll
            for (int i = 0; i < 4; ++i)
                ldsm4(a[i][0], a[i][1], a[i][2], a[i][3], sb + offA[kk][i]);
            #pragma unroll
            for (int jp = 0; jp < 2; ++jp)
                ldsm4(b[jp][0], b[jp][1], b[jp][2], b[jp][3], sb + offB[kk][jp]);
            #pragma unroll
            for (int i = 0; i < 4; ++i)
                #pragma unroll
                for (int j = 0; j < 4; ++j)
                    mma16816(acc[i][j], a[i], b[j >> 1][(j & 1) * 2 + 0], b[j >> 1][(j & 1) * 2 + 1]);
        }
    }

    const int qid = lane >> 2;
    const int ql  = (lane & 3) << 1;
    #pragma unroll
    for (int i = 0; i < 4; ++i) {
        const int gp0 = bm + wm + i * 16 + qid;
        float dh0 = -HOMEO * (rr[gp0]     - TARGET_RATE);
        float dh1 = -HOMEO * (rr[gp0 + 8] - TARGET_RATE);
        #pragma unroll
        for (int j = 0; j < 4; ++j) {
            const int gq = bn + wn + j * 8 + ql;
            const size_t o0 = (size_t)gp0 * Nld + gq;
            const size_t o1 = o0 + (size_t)8 * Nld;
            float2 w0 = *(const float2*)(W + o0);
            float2 w1 = *(const float2*)(W + o1);
            float x0 = fminf(fmaxf(w0.x + acc[i][j][0] + dh0, W_MINV), W_MAXV);
            float x1 = fminf(fmaxf(w0.y + acc[i][j][1] + dh0, W_MINV), W_MAXV);
            float y0 = fminf(fmaxf(w1.x + acc[i][j][2] + dh1, W_MINV), W_MAXV);
            float y1 = fminf(fmaxf(w1.y + acc[i][j][3] + dh1, W_MINV), W_MAXV);
            *(float2*)(Out + o0) = make_float2(x0, x1);
            *(float2*)(Out + o1) = make_float2(y0, y1);
            union { __nv_bfloat162 h; uint32_t u; } c0, c1;
            c0.h = __float22bfloat162_rn(make_float2(x0, x1));
            c1.h = __float22bfloat162_rn(make_float2(y0, y1));
            *(uint32_t*)(OutB + o0) = c0.u;
            *(uint32_t*)(OutB + o1) = c1.u;
        }
    }
}

// ============================================================
// GEMM2 (current): 128x128 CTA tile, 128 threads (4 warps,
// 2x2 warp grid of 64x64) -> ldsm traffic cut 35%.
// BK=64, 3-stage, 96KB smem, 2 CTAs/SM.  Resets g_trace_nz.
// ============================================================
__global__ void __launch_bounds__(128, 2)
gemm2_mma(const __nv_bfloat16* __restrict__ A,
          const __nv_bfloat16* __restrict__ Bmat,
          float* __restrict__ Out,
          int Ktot, int Nld)
{
    const int tid = threadIdx.x;
    if (tid == 0 && blockIdx.x == 0 && blockIdx.y == 0) g_trace_nz = 0;

    extern __shared__ char smraw[];
    const uint32_t sbase = smem_u32(smraw);
    const int wid  = tid >> 5;       // 0..3
    const int lane = tid & 31;
    const int bm = blockIdx.y << 7;
    const int bn = blockIdx.x << 7;
    const int wm = (wid & 1) << 6;   // 0 / 64
    const int wn = (wid >> 1) << 6;  // 0 / 64

    // ldmatrix offsets, kk in {0,1}; kk in {2,3} via ^64
    const int grp = lane >> 3, rowin = lane & 7;
    uint32_t offA[2][4], offB[2][4];
    #pragma unroll
    for (int kk = 0; kk < 2; ++kk) {
        #pragma unroll
        for (int i = 0; i < 4; ++i) {
            int row = wm + i * 16 + ((grp & 1) << 3) + rowin;
            int ch  = (kk << 1) + (grp >> 1);
            int sw  = ch ^ (row & 7);
            offA[kk][i] = (uint32_t)(row * 128 + sw * 16);
        }
        #pragma unroll
        for (int j = 0; j < 4; ++j) {
            int row = wn + j * 16 + ((grp >> 1) << 3) + rowin;
            int ch  = (kk << 1) + (grp & 1);
            int sw  = ch ^ (row & 7);
            offB[kk][j] = (uint32_t)(16384 + row * 128 + sw * 16);
        }
    }

    const __nv_bfloat16* Ag = A    + (size_t)bm * Ktot;
    const __nv_bfloat16* Bg = Bmat + (size_t)bn * Ktot;

    float acc[4][8][4];
    #pragma unroll
    for (int i = 0; i < 4; ++i)
        #pragma unroll
        for (int j = 0; j < 8; ++j)
            #pragma unroll
            for (int r = 0; r < 4; ++r) acc[i][j][r] = 0.f;

    const int NK = Ktot >> 6;          // BK=64
    const uint32_t SST = 32768u;

    // cp.async: 8 A + 8 B transfers per thread per stage (computed on the fly)
    #pragma unroll
    for (int s = 0; s < 2; ++s) {
        uint32_t sb = sbase + (uint32_t)s * SST;
        int k0 = s << 6;
        #pragma unroll
        for (int i = 0; i < 8; ++i) {
            int flat = tid + (i << 7);          // 0..1023
            int row = flat >> 3, ch = flat & 7;
            uint32_t so = (uint32_t)(row * 128 + ((ch ^ (row & 7)) << 4));
            const void* pa = Ag + (size_t)row * Ktot + k0 + (ch << 3);
            asm volatile("cp.async.cg.shared.global [%0], [%1], 16;" :: "r"(sb + so), "l"(pa));
            const void* pb = Bg + (size_t)row * Ktot + k0 + (ch << 3);
            asm volatile("cp.async.cg.shared.global [%0], [%1], 16;" :: "r"(sb + 16384u + so), "l"(pb));
        }
        asm volatile("cp.async.commit_group;" ::: "memory");
    }

    for (int it = 0; it < NK; ++it) {
        if (it < NK - 1) asm volatile("cp.async.wait_group 1;" ::: "memory");
        else             asm volatile("cp.async.wait_group 0;" ::: "memory");
        __syncthreads();

        if (it + 2 < NK) {
            uint32_t sb2 = sbase + (uint32_t)((it + 2) % 3) * SST;
            int k0 = (it + 2) << 6;
            #pragma unroll
            for (int i = 0; i < 8; ++i) {
                int flat = tid + (i << 7);
                int row = flat >> 3, ch = flat & 7;
                uint32_t so = (uint32_t)(row * 128 + ((ch ^ (row & 7)) << 4));
                const void* pa = Ag + (size_t)row * Ktot + k0 + (ch << 3);
                asm volatile("cp.async.cg.shared.global [%0], [%1], 16;" :: "r"(sb2 + so), "l"(pa));
                const void* pb = Bg + (size_t)row * Ktot + k0 + (ch << 3);
                asm volatile("cp.async.cg.shared.global [%0], [%1], 16;" :: "r"(sb2 + 16384u + so), "l"(pb));
            }
            asm volatile("cp.async.commit_group;" ::: "memory");
        }

        const uint32_t sb = sbase + (uint32_t)(it % 3) * SST;
        #pragma unroll
        for (int kk = 0; kk < 4; ++kk) {
            const uint32_t xm = (kk & 2) ? 64u : 0u;
            const int ki = kk & 1;
            uint32_t a[4][4], b[4][4];
            #pragma unroll
            for (int i = 0; i < 4; ++i)
                ldsm4(a[i][0], a[i][1], a[i][2], a[i][3], sb + (offA[ki][i] ^ xm));
            #pragma unroll
            for (int j = 0; j < 4; ++j)
                ldsm4(b[j][0], b[j][1], b[j][2], b[j][3], sb + (offB[ki][j] ^ xm));
            #pragma unroll
            for (int i = 0; i < 4; ++i)
                #pragma unroll
                for (int j = 0; j < 8; ++j)
                    mma16816(acc[i][j], a[i], b[j >> 1][(j & 1) * 2 + 0], b[j >> 1][(j & 1) * 2 + 1]);
        }
    }

    const int qid = lane >> 2;
    const int ql  = (lane & 3) << 1;
    #pragma unroll
    for (int i = 0; i < 4; ++i) {
        const int gp0 = bm + wm + i * 16 + qid;
        #pragma unroll
        for (int j = 0; j < 8; ++j) {
            const int gq = bn + wn + j * 8 + ql;
            const size_t o0 = (size_t)gp0 * Nld + gq;
            const size_t o1 = o0 + (size_t)8 * Nld;
            *(float2*)(Out + o0) = make_float2(acc[i][j][0], acc[i][j][1]);
            *(float2*)(Out + o1) = make_float2(acc[i][j][2], acc[i][j][3]);
        }
    }
}

// ============================================================
// Rate partials + EMA
// ============================================================
__global__ void __launch_bounds__(256)
rate_partial_kernel(const float* __restrict__ post_sp)
{
    const int c4  = blockIdx.x * 256 + threadIdx.x;
    const int chunk = blockIdx.y;
    const int rows = BB / RATE_CHUNKS;                  // 32
    const float4* base = (const float4*)(post_sp) + (size_t)chunk * rows * (POSTN / 4) + c4;
    float4 a0 = make_float4(0.f, 0.f, 0.f, 0.f);
    float4 a1 = make_float4(0.f, 0.f, 0.f, 0.f);
    #pragma unroll
    for (int r = 0; r < rows; r += 2) {
        float4 v0 = base[(size_t)r * (POSTN / 4)];
        float4 v1 = base[(size_t)(r + 1) * (POSTN / 4)];
        a0.x += v0.x; a0.y += v0.y; a0.z += v0.z; a0.w += v0.w;
        a1.x += v1.x; a1.y += v1.y; a1.z += v1.z; a1.w += v1.w;
    }
    float4 s;
    s.x = a0.x + a1.x; s.y = a0.y + a1.y; s.z = a0.z + a1.z; s.w = a0.w + a1.w;
    *((float4*)g_rate_partial + (size_t)chunk * (POSTN / 4) + c4) = s;
}

__global__ void __launch_bounds__(256)
rate_ema_kernel(const float* __restrict__ rr, float* __restrict__ new_rate)
{
    const int c4 = blockIdx.x * 256 + threadIdx.x;
    float4 s = make_float4(0.f, 0.f, 0.f, 0.f);
    #pragma unroll
    for (int c = 0; c < RATE_CHUNKS; ++c) {
        float4 v = *((const float4*)g_rate_partial + (size_t)c * (POSTN / 4) + c4);
        s.x += v.x; s.y += v.y; s.z += v.z; s.w += v.w;
    }
    float4 r = *((const float4*)rr + c4);
    float4 o;
    o.x = r.x * (1.0f - RATE_ALPHA) + RATE_ALPHA * (s.x / (float)BB);
    o.y = r.y * (1.0f - RATE_ALPHA) + RATE_ALPHA * (s.y / (float)BB);
    o.z = r.z * (1.0f - RATE_ALPHA) + RATE_ALPHA * (s.z / (float)BB);
    o.w = r.w * (1.0f - RATE_ALPHA) + RATE_ALPHA * (s.w / (float)BB);
    *((float4*)new_rate + c4) = o;
}

// ============================================================
// launch
// ============================================================
extern "C" void kernel_launch(void* const* d_in, const int* in_sizes, int n_in,
                              void* d_out, int out_size)
{
    const float* pre_sp  = (const float*)d_in[0];
    const float* post_sp = (const float*)d_in[1];
    const float* W       = (const float*)d_in[2];
    const float* pre_tr  = (const float*)d_in[3];
    const float* post_tr = (const float*)d_in[4];
    const float* rr      = (const float*)d_in[5];

    float* out = (float*)d_out;
    float* cur      = out;
    float* wn       = cur + (size_t)BB * POSTN;
    float* new_pre  = wn + (size_t)POSTN * PREN;
    float* new_post = new_pre + (size_t)BB * PREN;
    float* new_rate = new_post + (size_t)BB * POSTN;

    void *pA, *pB, *pPre, *pWb;
    cudaGetSymbolAddress(&pA,   g_A);
    cudaGetSymbolAddress(&pB,   g_Bm);
    cudaGetSymbolAddress(&pPre, g_preb);
    cudaGetSymbolAddress(&pWb,  g_Wb);

    const int SMEM1 = 4 * 16384;   // 64KB (wupdate GEMM path)
    const int SMEM2 = 3 * 32768;   // 96KB (gemm2, 3-stage BK=64)
    cudaFuncSetAttribute(wupdate_mma, cudaFuncAttributeMaxDynamicSharedMemorySize, SMEM1);
    cudaFuncSetAttribute(gemm2_mma,   cudaFuncAttributeMaxDynamicSharedMemorySize, SMEM2);

    // launch 0: traces + bf16(pre_spikes) + flag detection
    {
        long long n_pre4  = (long long)BB * PREN / 4;
        long long n_post4 = (long long)BB * POSTN / 4;
        prep_ew<<<2048, 256>>>((const float4*)pre_sp, (const float4*)pre_tr,
                               (const float4*)post_sp, (const float4*)post_tr,
                               (float4*)new_pre, (float4*)new_post,
                               (uint2*)pPre, n_pre4, n_post4);
    }

    // launch 1: K-major bf16 transposes (self-gated)
    {
        const float S0 = (A_PLUS * DECAYF) / (float)BB;
        const float S1 = -(A_MINUS * DECAYF) / (float)BB;
        dim3 g(4096 / 64, BB / 64);
        prep_tr4<<<g, 256>>>(post_sp, post_tr, pre_tr, pre_sp,
                             (__nv_bfloat16*)pA, (__nv_bfloat16*)pB, S0, S1);
    }

    // launch 2: weight update (combined fast/GEMM dispatch)
    {
        dim3 grid(PREN / 128, POSTN / 128);
        wupdate_mma<<<grid, 256, SMEM1>>>((const __nv_bfloat16*)pA,
                                          (const __nv_bfloat16*)pB,
                                          W, rr, wn, (__nv_bfloat16*)pWb, K1, PREN);
    }

    // launch 3 (profiled slot): current = pre_spikes @ new_weights^T + flag reset
    {
        dim3 grid(POSTN / 128, BB / 128);
        gemm2_mma<<<grid, 128, SMEM2>>>((const __nv_bfloat16*)pPre,
                                        (const __nv_bfloat16*)pWb,
                                        cur, PREN, POSTN);
    }

    // launches 4,5: rate partials + EMA
    {
        dim3 g1(POSTN / 1024, RATE_CHUNKS);
        rate_partial_kernel<<<g1, 256>>>(post_sp);
        rate_ema_kernel<<<POSTN / 1024, 256>>>(rr, new_rate);
    }
}

// round 13
// speedup vs baseline: 1.0528x; 1.0345x over previous
#include <cuda_runtime.h>
#include <cuda_bf16.h>
#include <cstdint>

// ---------------- STDP constants ----------------
#define A_PLUS      0.01f
#define A_MINUS     0.01f
#define W_MAXV      1.0f
#define W_MINV      0.0f
#define TARGET_RATE 0.1f
#define HOMEO       0.001f
#define RATE_ALPHA  0.01f
#define DECAYF      0.9512294245007140f   // exp(-1/20)

// ---------------- fixed shapes ----------------
#define BB    1024
#define PREN  4096
#define POSTN 4096
#define K1    2048
#define RATE_CHUNKS 32

// ---------------- device scratch ----------------
__device__ __align__(128) __nv_bfloat16 g_A   [(size_t)POSTN * K1];
__device__ __align__(128) __nv_bfloat16 g_Bm  [(size_t)PREN  * K1];
__device__ __align__(128) __nv_bfloat16 g_preb[(size_t)BB    * PREN];
__device__ __align__(128) __nv_bfloat16 g_Wb  [(size_t)POSTN * PREN];
__device__ float g_rate_partial[RATE_CHUNKS * POSTN];
__device__ int   g_trace_nz;   // set by prep_ew; reset by gemm2

// ============================================================
// asm helpers
// ============================================================
__device__ __forceinline__ uint32_t smem_u32(const void* p) {
    uint32_t a;
    asm("{ .reg .u64 t; cvta.to.shared.u64 t, %1; cvt.u32.u64 %0, t; }" : "=r"(a) : "l"(p));
    return a;
}
__device__ __forceinline__ void ldsm4(uint32_t& r0, uint32_t& r1, uint32_t& r2, uint32_t& r3,
                                      uint32_t addr) {
    asm volatile("ldmatrix.sync.aligned.m8n8.x4.shared.b16 {%0,%1,%2,%3}, [%4];"
                 : "=r"(r0), "=r"(r1), "=r"(r2), "=r"(r3) : "r"(addr));
}
__device__ __forceinline__ void mma16816(float* c, const uint32_t* a, uint32_t b0, uint32_t b1) {
    asm volatile(
        "mma.sync.aligned.m16n8k16.row.col.f32.bf16.bf16.f32 "
        "{%0,%1,%2,%3}, {%4,%5,%6,%7}, {%8,%9}, {%0,%1,%2,%3};"
        : "+f"(c[0]), "+f"(c[1]), "+f"(c[2]), "+f"(c[3])
        : "r"(a[0]), "r"(a[1]), "r"(a[2]), "r"(a[3]), "r"(b0), "r"(b1));
}

// ============================================================
// Prep 1: traces + bf16(pre_spikes) + trace-nonzero detection
// ============================================================
__global__ void prep_ew(const float4* __restrict__ pre_sp,
                        const float4* __restrict__ pre_tr,
                        const float4* __restrict__ post_sp,
                        const float4* __restrict__ post_tr,
                        float4* __restrict__ new_pre,
                        float4* __restrict__ new_post,
                        uint2* __restrict__ preb,
                        long long n_pre4, long long n_post4)
{
    long long total = n_pre4 + n_post4;
    int nz = 0;
    for (long long i = (long long)blockIdx.x * blockDim.x + threadIdx.x;
         i < total; i += (long long)gridDim.x * blockDim.x) {
        if (i < n_pre4) {
            float4 s = pre_sp[i], t = pre_tr[i];
            if (t.x != 0.f || t.y != 0.f || t.z != 0.f || t.w != 0.f) nz |= 1;
            float4 o;
            o.x = t.x * DECAYF + s.x; o.y = t.y * DECAYF + s.y;
            o.z = t.z * DECAYF + s.z; o.w = t.w * DECAYF + s.w;
            new_pre[i] = o;
            __nv_bfloat162 b0 = __float22bfloat162_rn(make_float2(s.x, s.y));
            __nv_bfloat162 b1 = __float22bfloat162_rn(make_float2(s.z, s.w));
            union { __nv_bfloat162 h[2]; uint2 u; } cv; cv.h[0] = b0; cv.h[1] = b1;
            preb[i] = cv.u;
        } else {
            long long j = i - n_pre4;
            float4 s = post_sp[j], t = post_tr[j];
            if (t.x != 0.f || t.y != 0.f || t.z != 0.f || t.w != 0.f) nz |= 2;
            float4 o;
            o.x = t.x * DECAYF + s.x; o.y = t.y * DECAYF + s.y;
            o.z = t.z * DECAYF + s.z; o.w = t.w * DECAYF + s.w;
            new_post[j] = o;
        }
    }
    unsigned m1 = __ballot_sync(0xffffffffu, nz & 1);
    unsigned m2 = __ballot_sync(0xffffffffu, nz & 2);
    if ((threadIdx.x & 31) == 0) {
        int v = (m1 ? 1 : 0) | (m2 ? 2 : 0);
        if (v) atomicOr(&g_trace_nz, v);
    }
}

// ============================================================
// Prep 2: transpose + scale + bf16, 4 slices via internal z loop
// ============================================================
__global__ void __launch_bounds__(256)
prep_tr4(const float* __restrict__ x0, const float* __restrict__ x1,
         const float* __restrict__ x2, const float* __restrict__ x3,
         __nv_bfloat16* __restrict__ yA, __nv_bfloat16* __restrict__ yB,
         float s0, float s1)
{
    if (g_trace_nz == 0) return;
    __shared__ float tf[64][65];
    const int m0 = blockIdx.x << 6;
    const int k0 = blockIdx.y << 6;
    const int tid = threadIdx.x;
    #pragma unroll 1
    for (int z = 0; z < 4; ++z) {
        const float* X = (z == 0) ? x0 : (z == 1) ? x1 : (z == 2) ? x2 : x3;
        __nv_bfloat16* Y = (z < 2) ? yA : yB;
        const float scale = (z == 0) ? s0 : (z == 1) ? s1 : 1.0f;
        const int koff = (z & 1) ? BB : 0;
        #pragma unroll
        for (int i = 0; i < 4; ++i) {
            int flat = tid + (i << 8);
            int kr = flat >> 4;
            int mc = (flat & 15) << 2;
            float4 v = *(const float4*)(X + (size_t)(k0 + kr) * 4096 + m0 + mc);
            tf[kr][mc + 0] = v.x; tf[kr][mc + 1] = v.y;
            tf[kr][mc + 2] = v.z; tf[kr][mc + 3] = v.w;
        }
        __syncthreads();
        int m = tid >> 2;
        int seg = (tid & 3) << 4;
        __align__(16) __nv_bfloat16 buf[16];
        #pragma unroll
        for (int j = 0; j < 16; ++j)
            buf[j] = __float2bfloat16(tf[seg + j][m] * scale);
        __nv_bfloat16* dst = Y + (size_t)(m0 + m) * K1 + koff + k0 + seg;
        *(uint4*)(dst)     = *(uint4*)&buf[0];
        *(uint4*)(dst + 8) = *(uint4*)&buf[8];
        __syncthreads();
    }
}

// ============================================================
// Weight update (combined) + FUSED rate partial sums.
// Blocks with bx in [28,32) also compute rate chunk = by,
// col-group = bx-28 (runs on both fast and GEMM paths).
// ============================================================
__global__ void __launch_bounds__(256, 2)
wupdate_mma(const __nv_bfloat16* __restrict__ A,
            const __nv_bfloat16* __restrict__ Bmat,
            const float* __restrict__ post_sp,
            const float* __restrict__ W,
            const float* __restrict__ rr,
            float* __restrict__ Out,
            __nv_bfloat16* __restrict__ OutB,
            int Ktot, int Nld)
{
    const int tid = threadIdx.x;
    const int bm = blockIdx.y << 7;
    const int bn = blockIdx.x << 7;

    // fused rate_partial: 4 col-groups x 32 chunks (post_sp independent of W path)
    if (blockIdx.x >= 28) {
        const int c4 = (blockIdx.x - 28) * 256 + tid;
        const int chunk = blockIdx.y;
        const int rows = BB / RATE_CHUNKS;               // 32
        const float4* base = (const float4*)(post_sp) + (size_t)chunk * rows * (POSTN / 4) + c4;
        float4 a0 = make_float4(0.f, 0.f, 0.f, 0.f);
        float4 a1 = make_float4(0.f, 0.f, 0.f, 0.f);
        #pragma unroll
        for (int r = 0; r < rows; r += 2) {
            float4 v0 = base[(size_t)r * (POSTN / 4)];
            float4 v1 = base[(size_t)(r + 1) * (POSTN / 4)];
            a0.x += v0.x; a0.y += v0.y; a0.z += v0.z; a0.w += v0.w;
            a1.x += v1.x; a1.y += v1.y; a1.z += v1.z; a1.w += v1.w;
        }
        float4 s;
        s.x = a0.x + a1.x; s.y = a0.y + a1.y; s.z = a0.z + a1.z; s.w = a0.w + a1.w;
        *((float4*)g_rate_partial + (size_t)chunk * (POSTN / 4) + c4) = s;
    }

    if (g_trace_nz == 0) {
        #pragma unroll 1
        for (int b2 = 0; b2 < 4; ++b2) {
            float4 wv[4];
            float  dhv[4];
            size_t ov[4];
            #pragma unroll
            for (int u = 0; u < 4; ++u) {
                int flat = tid + ((b2 * 4 + u) << 8);
                int row  = flat >> 5;
                int c4   = (flat & 31) << 2;
                int gp   = bm + row;
                ov[u]  = (size_t)gp * PREN + bn + c4;
                dhv[u] = -HOMEO * (rr[gp] - TARGET_RATE);
                wv[u]  = *(const float4*)(W + ov[u]);
            }
            #pragma unroll
            for (int u = 0; u < 4; ++u) {
                float4 w = wv[u];
                float dh = dhv[u];
                w.x = fminf(fmaxf(w.x + dh, W_MINV), W_MAXV);
                w.y = fminf(fmaxf(w.y + dh, W_MINV), W_MAXV);
                w.z = fminf(fmaxf(w.z + dh, W_MINV), W_MAXV);
                w.w = fminf(fmaxf(w.w + dh, W_MINV), W_MAXV);
                *(float4*)(Out + ov[u]) = w;
                __nv_bfloat162 b0 = __float22bfloat162_rn(make_float2(w.x, w.y));
                __nv_bfloat162 b1 = __float22bfloat162_rn(make_float2(w.z, w.w));
                union { __nv_bfloat162 h[2]; uint2 u2; } cv; cv.h[0] = b0; cv.h[1] = b1;
                *(uint2*)(OutB + ov[u]) = cv.u2;
            }
        }
        return;
    }

    extern __shared__ char smraw[];
    const uint32_t sbase = smem_u32(smraw);
    const int wid  = tid >> 5;
    const int lane = tid & 31;
    const int wm = (wid & 1) << 6;
    const int wn = (wid >> 1) << 5;

    uint32_t st_off[2];
    int g_row[2], g_col[2];
    #pragma unroll
    for (int i = 0; i < 2; ++i) {
        int flat = tid + (i << 8);
        int row = flat >> 2, ch = flat & 3;
        int sw = ch ^ ((row >> 1) & 3);
        st_off[i] = (uint32_t)(row * 64 + sw * 16);
        g_row[i] = row; g_col[i] = ch * 8;
    }

    const int grp = lane >> 3, rowin = lane & 7;
    uint32_t offA[2][4], offB[2][2];
    #pragma unroll
    for (int kk = 0; kk < 2; ++kk) {
        #pragma unroll
        for (int i = 0; i < 4; ++i) {
            int row = wm + i * 16 + ((grp & 1) << 3) + rowin;
            int ch  = (kk << 1) + (grp >> 1);
            int sw  = ch ^ ((row >> 1) & 3);
            offA[kk][i] = (uint32_t)(row * 64 + sw * 16);
        }
        #pragma unroll
        for (int jp = 0; jp < 2; ++jp) {
            int row = wn + jp * 16 + ((grp >> 1) << 3) + rowin;
            int ch  = (kk << 1) + (grp & 1);
            int sw  = ch ^ ((row >> 1) & 3);
            offB[kk][jp] = (uint32_t)(8192 + row * 64 + sw * 16);
        }
    }

    const __nv_bfloat16* Ag = A    + (size_t)bm * Ktot;
    const __nv_bfloat16* Bg = Bmat + (size_t)bn * Ktot;

    float acc[4][4][4];
    #pragma unroll
    for (int i = 0; i < 4; ++i)
        #pragma unroll
        for (int j = 0; j < 4; ++j)
            #pragma unroll
            for (int r = 0; r < 4; ++r) acc[i][j][r] = 0.f;

    const int NK = Ktot >> 5;

    #pragma unroll
    for (int s = 0; s < 3; ++s) {
        uint32_t sb = sbase + (uint32_t)s * 16384u;
        int k0 = s << 5;
        #pragma unroll
        for (int i = 0; i < 2; ++i) {
            const void* pa = Ag + (size_t)g_row[i] * Ktot + k0 + g_col[i];
            asm volatile("cp.async.cg.shared.global [%0], [%1], 16;" :: "r"(sb + st_off[i]), "l"(pa));
        }
        #pragma unroll
        for (int i = 0; i < 2; ++i) {
            const void* pb = Bg + (size_t)g_row[i] * Ktot + k0 + g_col[i];
            asm volatile("cp.async.cg.shared.global [%0], [%1], 16;" :: "r"(sb + 8192u + st_off[i]), "l"(pb));
        }
        asm volatile("cp.async.commit_group;" ::: "memory");
    }

    for (int it = 0; it < NK; ++it) {
        const int s = it & 3;
        if (it < NK - 2)       asm volatile("cp.async.wait_group 2;" ::: "memory");
        else if (it == NK - 2) asm volatile("cp.async.wait_group 1;" ::: "memory");
        else                   asm volatile("cp.async.wait_group 0;" ::: "memory");
        __syncthreads();

        if (it + 3 < NK) {
            uint32_t sb2 = sbase + (uint32_t)((it + 3) & 3) * 16384u;
            int k0 = (it + 3) << 5;
            #pragma unroll
            for (int i = 0; i < 2; ++i) {
                const void* pa = Ag + (size_t)g_row[i] * Ktot + k0 + g_col[i];
                asm volatile("cp.async.cg.shared.global [%0], [%1], 16;" :: "r"(sb2 + st_off[i]), "l"(pa));
            }
            #pragma unroll
            for (int i = 0; i < 2; ++i) {
                const void* pb = Bg + (size_t)g_row[i] * Ktot + k0 + g_col[i];
                asm volatile("cp.async.cg.shared.global [%0], [%1], 16;" :: "r"(sb2 + 8192u + st_off[i]), "l"(pb));
            }
            asm volatile("cp.async.commit_group;" ::: "memory");
        }

        const uint32_t sb = sbase + (uint32_t)s * 16384u;
        #pragma unroll
        for (int kk = 0; kk < 2; ++kk) {
            uint32_t a[4][4], b[2][4];
            #pragma unroll
            for (int i = 0; i < 4; ++i)
                ldsm4(a[i][0], a[i][1], a[i][2], a[i][3], sb + offA[kk][i]);
            #pragma unroll
            for (int jp = 0; jp < 2; ++jp)
                ldsm4(b[jp][0], b[jp][1], b[jp][2], b[jp][3], sb + offB[kk][jp]);
            #pragma unroll
            for (int i = 0; i < 4; ++i)
                #pragma unroll
                for (int j = 0; j < 4; ++j)
                    mma16816(acc[i][j], a[i], b[j >> 1][(j & 1) * 2 + 0], b[j >> 1][(j & 1) * 2 + 1]);
        }
    }

    const int qid = lane >> 2;
    const int ql  = (lane & 3) << 1;
    #pragma unroll
    for (int i = 0; i < 4; ++i) {
        const int gp0 = bm + wm + i * 16 + qid;
        float dh0 = -HOMEO * (rr[gp0]     - TARGET_RATE);
        float dh1 = -HOMEO * (rr[gp0 + 8] - TARGET_RATE);
        #pragma unroll
        for (int j = 0; j < 4; ++j) {
            const int gq = bn + wn + j * 8 + ql;
            const size_t o0 = (size_t)gp0 * Nld + gq;
            const size_t o1 = o0 + (size_t)8 * Nld;
            float2 w0 = *(const float2*)(W + o0);
            float2 w1 = *(const float2*)(W + o1);
            float x0 = fminf(fmaxf(w0.x + acc[i][j][0] + dh0, W_MINV), W_MAXV);
            float x1 = fminf(fmaxf(w0.y + acc[i][j][1] + dh0, W_MINV), W_MAXV);
            float y0 = fminf(fmaxf(w1.x + acc[i][j][2] + dh1, W_MINV), W_MAXV);
            float y1 = fminf(fmaxf(w1.y + acc[i][j][3] + dh1, W_MINV), W_MAXV);
            *(float2*)(Out + o0) = make_float2(x0, x1);
            *(float2*)(Out + o1) = make_float2(y0, y1);
            union { __nv_bfloat162 h; uint32_t u; } c0, c1;
            c0.h = __float22bfloat162_rn(make_float2(x0, x1));
            c1.h = __float22bfloat162_rn(make_float2(y0, y1));
            *(uint32_t*)(OutB + o0) = c0.u;
            *(uint32_t*)(OutB + o1) = c1.u;
        }
    }
}

// ============================================================
// GEMM2: 128x128 CTA tile, 128 threads (2x2 warps of 64x64),
// BK=64, 3-stage, 96KB smem, 2 CTAs/SM.  FUSED: rate EMA
// (blocks by==0, bx<8) and g_trace_nz reset.
// ============================================================
__global__ void __launch_bounds__(128, 2)
gemm2_mma(const __nv_bfloat16* __restrict__ A,
          const __nv_bfloat16* __restrict__ Bmat,
          const float* __restrict__ rr,
          float* __restrict__ new_rate,
          float* __restrict__ Out,
          int Ktot, int Nld)
{
    const int tid = threadIdx.x;
    if (tid == 0 && blockIdx.x == 0 && blockIdx.y == 0) g_trace_nz = 0;

    // fused rate EMA: 8 blocks x 128 threads cover 1024 float4 columns
    if (blockIdx.y == 0 && blockIdx.x < 8) {
        const int c4 = blockIdx.x * 128 + tid;
        float4 s = make_float4(0.f, 0.f, 0.f, 0.f);
        #pragma unroll
        for (int c = 0; c < RATE_CHUNKS; ++c) {
            float4 v = *((const float4*)g_rate_partial + (size_t)c * (POSTN / 4) + c4);
            s.x += v.x; s.y += v.y; s.z += v.z; s.w += v.w;
        }
        float4 r = *((const float4*)rr + c4);
        float4 o;
        o.x = r.x * (1.0f - RATE_ALPHA) + RATE_ALPHA * (s.x / (float)BB);
        o.y = r.y * (1.0f - RATE_ALPHA) + RATE_ALPHA * (s.y / (float)BB);
        o.z = r.z * (1.0f - RATE_ALPHA) + RATE_ALPHA * (s.z / (float)BB);
        o.w = r.w * (1.0f - RATE_ALPHA) + RATE_ALPHA * (s.w / (float)BB);
        *((float4*)new_rate + c4) = o;
    }

    extern __shared__ char smraw[];
    const uint32_t sbase = smem_u32(smraw);
    const int wid  = tid >> 5;
    const int lane = tid & 31;
    const int bm = blockIdx.y << 7;
    const int bn = blockIdx.x << 7;
    const int wm = (wid & 1) << 6;
    const int wn = (wid >> 1) << 6;

    const int grp = lane >> 3, rowin = lane & 7;
    uint32_t offA[2][4], offB[2][4];
    #pragma unroll
    for (int kk = 0; kk < 2; ++kk) {
        #pragma unroll
        for (int i = 0; i < 4; ++i) {
            int row = wm + i * 16 + ((grp & 1) << 3) + rowin;
            int ch  = (kk << 1) + (grp >> 1);
            int sw  = ch ^ (row & 7);
            offA[kk][i] = (uint32_t)(row * 128 + sw * 16);
        }
        #pragma unroll
        for (int j = 0; j < 4; ++j) {
            int row = wn + j * 16 + ((grp >> 1) << 3) + rowin;
            int ch  = (kk << 1) + (grp & 1);
            int sw  = ch ^ (row & 7);
            offB[kk][j] = (uint32_t)(16384 + row * 128 + sw * 16);
        }
    }

    const __nv_bfloat16* Ag = A    + (size_t)bm * Ktot;
    const __nv_bfloat16* Bg = Bmat + (size_t)bn * Ktot;

    float acc[4][8][4];
    #pragma unroll
    for (int i = 0; i < 4; ++i)
        #pragma unroll
        for (int j = 0; j < 8; ++j)
            #pragma unroll
            for (int r = 0; r < 4; ++r) acc[i][j][r] = 0.f;

    const int NK = Ktot >> 6;
    const uint32_t SST = 32768u;

    #pragma unroll
    for (int s = 0; s < 2; ++s) {
        uint32_t sb = sbase + (uint32_t)s * SST;
        int k0 = s << 6;
        #pragma unroll
        for (int i = 0; i < 8; ++i) {
            int flat = tid + (i << 7);
            int row = flat >> 3, ch = flat & 7;
            uint32_t so = (uint32_t)(row * 128 + ((ch ^ (row & 7)) << 4));
            const void* pa = Ag + (size_t)row * Ktot + k0 + (ch << 3);
            asm volatile("cp.async.cg.shared.global [%0], [%1], 16;" :: "r"(sb + so), "l"(pa));
            const void* pb = Bg + (size_t)row * Ktot + k0 + (ch << 3);
            asm volatile("cp.async.cg.shared.global [%0], [%1], 16;" :: "r"(sb + 16384u + so), "l"(pb));
        }
        asm volatile("cp.async.commit_group;" ::: "memory");
    }

    for (int it = 0; it < NK; ++it) {
        if (it < NK - 1) asm volatile("cp.async.wait_group 1;" ::: "memory");
        else             asm volatile("cp.async.wait_group 0;" ::: "memory");
        __syncthreads();

        if (it + 2 < NK) {
            uint32_t sb2 = sbase + (uint32_t)((it + 2) % 3) * SST;
            int k0 = (it + 2) << 6;
            #pragma unroll
            for (int i = 0; i < 8; ++i) {
                int flat = tid + (i << 7);
                int row = flat >> 3, ch = flat & 7;
                uint32_t so = (uint32_t)(row * 128 + ((ch ^ (row & 7)) << 4));
                const void* pa = Ag + (size_t)row * Ktot + k0 + (ch << 3);
                asm volatile("cp.async.cg.shared.global [%0], [%1], 16;" :: "r"(sb2 + so), "l"(pa));
                const void* pb = Bg + (size_t)row * Ktot + k0 + (ch << 3);
                asm volatile("cp.async.cg.shared.global [%0], [%1], 16;" :: "r"(sb2 + 16384u + so), "l"(pb));
            }
            asm volatile("cp.async.commit_group;" ::: "memory");
        }

        const uint32_t sb = sbase + (uint32_t)(it % 3) * SST;
        #pragma unroll
        for (int kk = 0; kk < 4; ++kk) {
            const uint32_t xm = (kk & 2) ? 64u : 0u;
            const int ki = kk & 1;
            uint32_t a[4][4], b[4][4];
            #pragma unroll
            for (int i = 0; i < 4; ++i)
                ldsm4(a[i][0], a[i][1], a[i][2], a[i][3], sb + (offA[ki][i] ^ xm));
            #pragma unroll
            for (int j = 0; j < 4; ++j)
                ldsm4(b[j][0], b[j][1], b[j][2], b[j][3], sb + (offB[ki][j] ^ xm));
            #pragma unroll
            for (int i = 0; i < 4; ++i)
                #pragma unroll
                for (int j = 0; j < 8; ++j)
                    mma16816(acc[i][j], a[i], b[j >> 1][(j & 1) * 2 + 0], b[j >> 1][(j & 1) * 2 + 1]);
        }
    }

    const int qid = lane >> 2;
    const int ql  = (lane & 3) << 1;
    #pragma unroll
    for (int i = 0; i < 4; ++i) {
        const int gp0 = bm + wm + i * 16 + qid;
        #pragma unroll
        for (int j = 0; j < 8; ++j) {
            const int gq = bn + wn + j * 8 + ql;
            const size_t o0 = (size_t)gp0 * Nld + gq;
            const size_t o1 = o0 + (size_t)8 * Nld;
            *(float2*)(Out + o0) = make_float2(acc[i][j][0], acc[i][j][1]);
            *(float2*)(Out + o1) = make_float2(acc[i][j][2], acc[i][j][3]);
        }
    }
}

// ============================================================
// launch  (4 launches total)
// ============================================================
extern "C" void kernel_launch(void* const* d_in, const int* in_sizes, int n_in,
                              void* d_out, int out_size)
{
    const float* pre_sp  = (const float*)d_in[0];
    const float* post_sp = (const float*)d_in[1];
    const float* W       = (const float*)d_in[2];
    const float* pre_tr  = (const float*)d_in[3];
    const float* post_tr = (const float*)d_in[4];
    const float* rr      = (const float*)d_in[5];

    float* out = (float*)d_out;
    float* cur      = out;
    float* wn       = cur + (size_t)BB * POSTN;
    float* new_pre  = wn + (size_t)POSTN * PREN;
    float* new_post = new_pre + (size_t)BB * PREN;
    float* new_rate = new_post + (size_t)BB * POSTN;

    void *pA, *pB, *pPre, *pWb;
    cudaGetSymbolAddress(&pA,   g_A);
    cudaGetSymbolAddress(&pB,   g_Bm);
    cudaGetSymbolAddress(&pPre, g_preb);
    cudaGetSymbolAddress(&pWb,  g_Wb);

    const int SMEM1 = 4 * 16384;   // 64KB (wupdate GEMM path)
    const int SMEM2 = 3 * 32768;   // 96KB (gemm2)
    cudaFuncSetAttribute(wupdate_mma, cudaFuncAttributeMaxDynamicSharedMemorySize, SMEM1);
    cudaFuncSetAttribute(gemm2_mma,   cudaFuncAttributeMaxDynamicSharedMemorySize, SMEM2);

    // launch 0: traces + bf16(pre_spikes) + flag detection
    {
        long long n_pre4  = (long long)BB * PREN / 4;
        long long n_post4 = (long long)BB * POSTN / 4;
        prep_ew<<<2048, 256>>>((const float4*)pre_sp, (const float4*)pre_tr,
                               (const float4*)post_sp, (const float4*)post_tr,
                               (float4*)new_pre, (float4*)new_post,
                               (uint2*)pPre, n_pre4, n_post4);
    }

    // launch 1: K-major bf16 transposes (self-gated)
    {
        const float S0 = (A_PLUS * DECAYF) / (float)BB;
        const float S1 = -(A_MINUS * DECAYF) / (float)BB;
        dim3 g(4096 / 64, BB / 64);
        prep_tr4<<<g, 256>>>(post_sp, post_tr, pre_tr, pre_sp,
                             (__nv_bfloat16*)pA, (__nv_bfloat16*)pB, S0, S1);
    }

    // launch 2: weight update + fused rate partials
    {
        dim3 grid(PREN / 128, POSTN / 128);
        wupdate_mma<<<grid, 256, SMEM1>>>((const __nv_bfloat16*)pA,
                                          (const __nv_bfloat16*)pB,
                                          post_sp, W, rr, wn,
                                          (__nv_bfloat16*)pWb, K1, PREN);
    }

    // launch 3 (profiled slot): current GEMM + fused rate EMA + flag reset
    {
        dim3 grid(POSTN / 128, BB / 128);
        gemm2_mma<<<grid, 128, SMEM2>>>((const __nv_bfloat16*)pPre,
                                        (const __nv_bfloat16*)pWb,
                                        rr, new_rate, cur, PREN, POSTN);
    }
}

// round 14
// speedup vs baseline: 1.1027x; 1.0474x over previous
#include <cuda_runtime.h>
#include <cuda_bf16.h>
#include <cstdint>

// ---------------- STDP constants ----------------
#define A_PLUS      0.01f
#define A_MINUS     0.01f
#define W_MAXV      1.0f
#define W_MINV      0.0f
#define TARGET_RATE 0.1f
#define HOMEO       0.001f
#define RATE_ALPHA  0.01f
#define DECAYF      0.9512294245007140f   // exp(-1/20)

// ---------------- fixed shapes ----------------
#define BB    1024
#define PREN  4096
#define POSTN 4096
#define K1    2048
#define RATE_CHUNKS 32

// ---------------- device scratch ----------------
__device__ __align__(128) __nv_bfloat16 g_A   [(size_t)POSTN * K1];
__device__ __align__(128) __nv_bfloat16 g_Bm  [(size_t)PREN  * K1];
__device__ __align__(128) __nv_bfloat16 g_preb[(size_t)BB    * PREN];
__device__ __align__(128) __nv_bfloat16 g_Wb  [(size_t)POSTN * PREN];
__device__ float g_rate_partial[RATE_CHUNKS * POSTN];
__device__ int   g_trace_nz;   // set by prep_ew; reset by gemm2

// ============================================================
// asm helpers
// ============================================================
__device__ __forceinline__ uint32_t smem_u32(const void* p) {
    uint32_t a;
    asm("{ .reg .u64 t; cvta.to.shared.u64 t, %1; cvt.u32.u64 %0, t; }" : "=r"(a) : "l"(p));
    return a;
}
__device__ __forceinline__ void ldsm4(uint32_t& r0, uint32_t& r1, uint32_t& r2, uint32_t& r3,
                                      uint32_t addr) {
    asm volatile("ldmatrix.sync.aligned.m8n8.x4.shared.b16 {%0,%1,%2,%3}, [%4];"
                 : "=r"(r0), "=r"(r1), "=r"(r2), "=r"(r3) : "r"(addr));
}
__device__ __forceinline__ void mma16816(float* c, const uint32_t* a, uint32_t b0, uint32_t b1) {
    asm volatile(
        "mma.sync.aligned.m16n8k16.row.col.f32.bf16.bf16.f32 "
        "{%0,%1,%2,%3}, {%4,%5,%6,%7}, {%8,%9}, {%0,%1,%2,%3};"
        : "+f"(c[0]), "+f"(c[1]), "+f"(c[2]), "+f"(c[3])
        : "r"(a[0]), "r"(a[1]), "r"(a[2]), "r"(a[3]), "r"(b0), "r"(b1));
}

// ============================================================
// Prep 1: traces + bf16(pre_spikes) + trace-nonzero detection
// ============================================================
__global__ void prep_ew(const float4* __restrict__ pre_sp,
                        const float4* __restrict__ pre_tr,
                        const float4* __restrict__ post_sp,
                        const float4* __restrict__ post_tr,
                        float4* __restrict__ new_pre,
                        float4* __restrict__ new_post,
                        uint2* __restrict__ preb,
                        long long n_pre4, long long n_post4)
{
    long long total = n_pre4 + n_post4;
    int nz = 0;
    for (long long i = (long long)blockIdx.x * blockDim.x + threadIdx.x;
         i < total; i += (long long)gridDim.x * blockDim.x) {
        if (i < n_pre4) {
            float4 s = pre_sp[i], t = pre_tr[i];
            if (t.x != 0.f || t.y != 0.f || t.z != 0.f || t.w != 0.f) nz |= 1;
            float4 o;
            o.x = t.x * DECAYF + s.x; o.y = t.y * DECAYF + s.y;
            o.z = t.z * DECAYF + s.z; o.w = t.w * DECAYF + s.w;
            new_pre[i] = o;
            __nv_bfloat162 b0 = __float22bfloat162_rn(make_float2(s.x, s.y));
            __nv_bfloat162 b1 = __float22bfloat162_rn(make_float2(s.z, s.w));
            union { __nv_bfloat162 h[2]; uint2 u; } cv; cv.h[0] = b0; cv.h[1] = b1;
            preb[i] = cv.u;
        } else {
            long long j = i - n_pre4;
            float4 s = post_sp[j], t = post_tr[j];
            if (t.x != 0.f || t.y != 0.f || t.z != 0.f || t.w != 0.f) nz |= 2;
            float4 o;
            o.x = t.x * DECAYF + s.x; o.y = t.y * DECAYF + s.y;
            o.z = t.z * DECAYF + s.z; o.w = t.w * DECAYF + s.w;
            new_post[j] = o;
        }
    }
    unsigned m1 = __ballot_sync(0xffffffffu, nz & 1);
    unsigned m2 = __ballot_sync(0xffffffffu, nz & 2);
    if ((threadIdx.x & 31) == 0) {
        int v = (m1 ? 1 : 0) | (m2 ? 2 : 0);
        if (v) atomicOr(&g_trace_nz, v);
    }
}

// ============================================================
// Prep 2: transpose + scale + bf16, 4 slices via internal z loop
// ============================================================
__global__ void __launch_bounds__(256)
prep_tr4(const float* __restrict__ x0, const float* __restrict__ x1,
         const float* __restrict__ x2, const float* __restrict__ x3,
         __nv_bfloat16* __restrict__ yA, __nv_bfloat16* __restrict__ yB,
         float s0, float s1)
{
    if (g_trace_nz == 0) return;
    __shared__ float tf[64][65];
    const int m0 = blockIdx.x << 6;
    const int k0 = blockIdx.y << 6;
    const int tid = threadIdx.x;
    #pragma unroll 1
    for (int z = 0; z < 4; ++z) {
        const float* X = (z == 0) ? x0 : (z == 1) ? x1 : (z == 2) ? x2 : x3;
        __nv_bfloat16* Y = (z < 2) ? yA : yB;
        const float scale = (z == 0) ? s0 : (z == 1) ? s1 : 1.0f;
        const int koff = (z & 1) ? BB : 0;
        #pragma unroll
        for (int i = 0; i < 4; ++i) {
            int flat = tid + (i << 8);
            int kr = flat >> 4;
            int mc = (flat & 15) << 2;
            float4 v = *(const float4*)(X + (size_t)(k0 + kr) * 4096 + m0 + mc);
            tf[kr][mc + 0] = v.x; tf[kr][mc + 1] = v.y;
            tf[kr][mc + 2] = v.z; tf[kr][mc + 3] = v.w;
        }
        __syncthreads();
        int m = tid >> 2;
        int seg = (tid & 3) << 4;
        __align__(16) __nv_bfloat16 buf[16];
        #pragma unroll
        for (int j = 0; j < 16; ++j)
            buf[j] = __float2bfloat16(tf[seg + j][m] * scale);
        __nv_bfloat16* dst = Y + (size_t)(m0 + m) * K1 + koff + k0 + seg;
        *(uint4*)(dst)     = *(uint4*)&buf[0];
        *(uint4*)(dst + 8) = *(uint4*)&buf[8];
        __syncthreads();
    }
}

// ============================================================
// Weight update (combined) + FUSED rate partial sums.
// ============================================================
__global__ void __launch_bounds__(256, 2)
wupdate_mma(const __nv_bfloat16* __restrict__ A,
            const __nv_bfloat16* __restrict__ Bmat,
            const float* __restrict__ post_sp,
            const float* __restrict__ W,
            const float* __restrict__ rr,
            float* __restrict__ Out,
            __nv_bfloat16* __restrict__ OutB,
            int Ktot, int Nld)
{
    const int tid = threadIdx.x;
    const int bm = blockIdx.y << 7;
    const int bn = blockIdx.x << 7;

    // fused rate_partial: 4 col-groups x 32 chunks
    if (blockIdx.x >= 28) {
        const int c4 = (blockIdx.x - 28) * 256 + tid;
        const int chunk = blockIdx.y;
        const int rows = BB / RATE_CHUNKS;               // 32
        const float4* base = (const float4*)(post_sp) + (size_t)chunk * rows * (POSTN / 4) + c4;
        float4 a0 = make_float4(0.f, 0.f, 0.f, 0.f);
        float4 a1 = make_float4(0.f, 0.f, 0.f, 0.f);
        #pragma unroll
        for (int r = 0; r < rows; r += 2) {
            float4 v0 = base[(size_t)r * (POSTN / 4)];
            float4 v1 = base[(size_t)(r + 1) * (POSTN / 4)];
            a0.x += v0.x; a0.y += v0.y; a0.z += v0.z; a0.w += v0.w;
            a1.x += v1.x; a1.y += v1.y; a1.z += v1.z; a1.w += v1.w;
        }
        float4 s;
        s.x = a0.x + a1.x; s.y = a0.y + a1.y; s.z = a0.z + a1.z; s.w = a0.w + a1.w;
        *((float4*)g_rate_partial + (size_t)chunk * (POSTN / 4) + c4) = s;
    }

    if (g_trace_nz == 0) {
        // elementwise fast path with 8-deep load batches (MLP)
        #pragma unroll 1
        for (int b2 = 0; b2 < 2; ++b2) {
            float4 wv[8];
            float  dhv[8];
            size_t ov[8];
            #pragma unroll
            for (int u = 0; u < 8; ++u) {
                int flat = tid + ((b2 * 8 + u) << 8);
                int row  = flat >> 5;
                int c4   = (flat & 31) << 2;
                int gp   = bm + row;
                ov[u]  = (size_t)gp * PREN + bn + c4;
                dhv[u] = -HOMEO * (rr[gp] - TARGET_RATE);
                wv[u]  = *(const float4*)(W + ov[u]);
            }
            #pragma unroll
            for (int u = 0; u < 8; ++u) {
                float4 w = wv[u];
                float dh = dhv[u];
                w.x = fminf(fmaxf(w.x + dh, W_MINV), W_MAXV);
                w.y = fminf(fmaxf(w.y + dh, W_MINV), W_MAXV);
                w.z = fminf(fmaxf(w.z + dh, W_MINV), W_MAXV);
                w.w = fminf(fmaxf(w.w + dh, W_MINV), W_MAXV);
                *(float4*)(Out + ov[u]) = w;
                __nv_bfloat162 b0 = __float22bfloat162_rn(make_float2(w.x, w.y));
                __nv_bfloat162 b1 = __float22bfloat162_rn(make_float2(w.z, w.w));
                union { __nv_bfloat162 h[2]; uint2 u2; } cv; cv.h[0] = b0; cv.h[1] = b1;
                *(uint2*)(OutB + ov[u]) = cv.u2;
            }
        }
        return;
    }

    extern __shared__ char smraw[];
    const uint32_t sbase = smem_u32(smraw);
    const int wid  = tid >> 5;
    const int lane = tid & 31;
    const int wm = (wid & 1) << 6;
    const int wn = (wid >> 1) << 5;

    uint32_t st_off[2];
    int g_row[2], g_col[2];
    #pragma unroll
    for (int i = 0; i < 2; ++i) {
        int flat = tid + (i << 8);
        int row = flat >> 2, ch = flat & 3;
        int sw = ch ^ ((row >> 1) & 3);
        st_off[i] = (uint32_t)(row * 64 + sw * 16);
        g_row[i] = row; g_col[i] = ch * 8;
    }

    const int grp = lane >> 3, rowin = lane & 7;
    uint32_t offA[2][4], offB[2][2];
    #pragma unroll
    for (int kk = 0; kk < 2; ++kk) {
        #pragma unroll
        for (int i = 0; i < 4; ++i) {
            int row = wm + i * 16 + ((grp & 1) << 3) + rowin;
            int ch  = (kk << 1) + (grp >> 1);
            int sw  = ch ^ ((row >> 1) & 3);
            offA[kk][i] = (uint32_t)(row * 64 + sw * 16);
        }
        #pragma unroll
        for (int jp = 0; jp < 2; ++jp) {
            int row = wn + jp * 16 + ((grp >> 1) << 3) + rowin;
            int ch  = (kk << 1) + (grp & 1);
            int sw  = ch ^ ((row >> 1) & 3);
            offB[kk][jp] = (uint32_t)(8192 + row * 64 + sw * 16);
        }
    }

    const __nv_bfloat16* Ag = A    + (size_t)bm * Ktot;
    const __nv_bfloat16* Bg = Bmat + (size_t)bn * Ktot;

    float acc[4][4][4];
    #pragma unroll
    for (int i = 0; i < 4; ++i)
        #pragma unroll
        for (int j = 0; j < 4; ++j)
            #pragma unroll
            for (int r = 0; r < 4; ++r) acc[i][j][r] = 0.f;

    const int NK = Ktot >> 5;

    #pragma unroll
    for (int s = 0; s < 3; ++s) {
        uint32_t sb = sbase + (uint32_t)s * 16384u;
        int k0 = s << 5;
        #pragma unroll
        for (int i = 0; i < 2; ++i) {
            const void* pa = Ag + (size_t)g_row[i] * Ktot + k0 + g_col[i];
            asm volatile("cp.async.cg.shared.global [%0], [%1], 16;" :: "r"(sb + st_off[i]), "l"(pa));
        }
        #pragma unroll
        for (int i = 0; i < 2; ++i) {
            const void* pb = Bg + (size_t)g_row[i] * Ktot + k0 + g_col[i];
            asm volatile("cp.async.cg.shared.global [%0], [%1], 16;" :: "r"(sb + 8192u + st_off[i]), "l"(pb));
        }
        asm volatile("cp.async.commit_group;" ::: "memory");
    }

    for (int it = 0; it < NK; ++it) {
        const int s = it & 3;
        if (it < NK - 2)       asm volatile("cp.async.wait_group 2;" ::: "memory");
        else if (it == NK - 2) asm volatile("cp.async.wait_group 1;" ::: "memory");
        else                   asm volatile("cp.async.wait_group 0;" ::: "memory");
        __syncthreads();

        if (it + 3 < NK) {
            uint32_t sb2 = sbase + (uint32_t)((it + 3) & 3) * 16384u;
            int k0 = (it + 3) << 5;
            #pragma unroll
            for (int i = 0; i < 2; ++i) {
                const void* pa = Ag + (size_t)g_row[i] * Ktot + k0 + g_col[i];
                asm volatile("cp.async.cg.shared.global [%0], [%1], 16;" :: "r"(sb2 + st_off[i]), "l"(pa));
            }
            #pragma unroll
            for (int i = 0; i < 2; ++i) {
                const void* pb = Bg + (size_t)g_row[i] * Ktot + k0 + g_col[i];
                asm volatile("cp.async.cg.shared.global [%0], [%1], 16;" :: "r"(sb2 + 8192u + st_off[i]), "l"(pb));
            }
            asm volatile("cp.async.commit_group;" ::: "memory");
        }

        const uint32_t sb = sbase + (uint32_t)s * 16384u;
        #pragma unroll
        for (int kk = 0; kk < 2; ++kk) {
            uint32_t a[4][4], b[2][4];
            #pragma unroll
            for (int i = 0; i < 4; ++i)
                ldsm4(a[i][0], a[i][1], a[i][2], a[i][3], sb + offA[kk][i]);
            #pragma unroll
            for (int jp = 0; jp < 2; ++jp)
                ldsm4(b[jp][0], b[jp][1], b[jp][2], b[jp][3], sb + offB[kk][jp]);
            #pragma unroll
            for (int i = 0; i < 4; ++i)
                #pragma unroll
                for (int j = 0; j < 4; ++j)
                    mma16816(acc[i][j], a[i], b[j >> 1][(j & 1) * 2 + 0], b[j >> 1][(j & 1) * 2 + 1]);
        }
    }

    const int qid = lane >> 2;
    const int ql  = (lane & 3) << 1;
    #pragma unroll
    for (int i = 0; i < 4; ++i) {
        const int gp0 = bm + wm + i * 16 + qid;
        float dh0 = -HOMEO * (rr[gp0]     - TARGET_RATE);
        float dh1 = -HOMEO * (rr[gp0 + 8] - TARGET_RATE);
        #pragma unroll
        for (int j = 0; j < 4; ++j) {
            const int gq = bn + wn + j * 8 + ql;
            const size_t o0 = (size_t)gp0 * Nld + gq;
            const size_t o1 = o0 + (size_t)8 * Nld;
            float2 w0 = *(const float2*)(W + o0);
            float2 w1 = *(const float2*)(W + o1);
            float x0 = fminf(fmaxf(w0.x + acc[i][j][0] + dh0, W_MINV), W_MAXV);
            float x1 = fminf(fmaxf(w0.y + acc[i][j][1] + dh0, W_MINV), W_MAXV);
            float y0 = fminf(fmaxf(w1.x + acc[i][j][2] + dh1, W_MINV), W_MAXV);
            float y1 = fminf(fmaxf(w1.y + acc[i][j][3] + dh1, W_MINV), W_MAXV);
            *(float2*)(Out + o0) = make_float2(x0, x1);
            *(float2*)(Out + o1) = make_float2(y0, y1);
            union { __nv_bfloat162 h; uint32_t u; } c0, c1;
            c0.h = __float22bfloat162_rn(make_float2(x0, x1));
            c1.h = __float22bfloat162_rn(make_float2(y0, y1));
            *(uint32_t*)(OutB + o0) = c0.u;
            *(uint32_t*)(OutB + o1) = c1.u;
        }
    }
}

// ============================================================
// GEMM2: 128x128 CTA tile, 128 threads (2x2 warps of 64x64),
// BK=64, 3-stage, 96KB smem, 2 CTAs/SM.  FUSED: rate EMA
// spread thinly across 32 blocks (by==0, warp 0, 1 col/lane)
// and g_trace_nz reset.
// ============================================================
__global__ void __launch_bounds__(128, 2)
gemm2_mma(const __nv_bfloat16* __restrict__ A,
          const __nv_bfloat16* __restrict__ Bmat,
          const float* __restrict__ rr,
          float* __restrict__ new_rate,
          float* __restrict__ Out,
          int Ktot, int Nld)
{
    const int tid = threadIdx.x;
    if (tid == 0 && blockIdx.x == 0 && blockIdx.y == 0) g_trace_nz = 0;

    // fused rate EMA: 32 blocks (by==0) x warp0 x 1 float4 column per lane
    if (blockIdx.y == 0 && tid < 32) {
        const int c4 = blockIdx.x * 32 + tid;
        float4 s = make_float4(0.f, 0.f, 0.f, 0.f);
        #pragma unroll
        for (int c = 0; c < RATE_CHUNKS; ++c) {
            float4 v = *((const float4*)g_rate_partial + (size_t)c * (POSTN / 4) + c4);
            s.x += v.x; s.y += v.y; s.z += v.z; s.w += v.w;
        }
        float4 r = *((const float4*)rr + c4);
        float4 o;
        o.x = r.x * (1.0f - RATE_ALPHA) + RATE_ALPHA * (s.x / (float)BB);
        o.y = r.y * (1.0f - RATE_ALPHA) + RATE_ALPHA * (s.y / (float)BB);
        o.z = r.z * (1.0f - RATE_ALPHA) + RATE_ALPHA * (s.z / (float)BB);
        o.w = r.w * (1.0f - RATE_ALPHA) + RATE_ALPHA * (s.w / (float)BB);
        *((float4*)new_rate + c4) = o;
    }

    extern __shared__ char smraw[];
    const uint32_t sbase = smem_u32(smraw);
    const int wid  = tid >> 5;
    const int lane = tid & 31;
    const int bm = blockIdx.y << 7;
    const int bn = blockIdx.x << 7;
    const int wm = (wid & 1) << 6;
    const int wn = (wid >> 1) << 6;

    const int grp = lane >> 3, rowin = lane & 7;
    uint32_t offA[2][4], offB[2][4];
    #pragma unroll
    for (int kk = 0; kk < 2; ++kk) {
        #pragma unroll
        for (int i = 0; i < 4; ++i) {
            int row = wm + i * 16 + ((grp & 1) << 3) + rowin;
            int ch  = (kk << 1) + (grp >> 1);
            int sw  = ch ^ (row & 7);
            offA[kk][i] = (uint32_t)(row * 128 + sw * 16);
        }
        #pragma unroll
        for (int j = 0; j < 4; ++j) {
            int row = wn + j * 16 + ((grp >> 1) << 3) + rowin;
            int ch  = (kk << 1) + (grp & 1);
            int sw  = ch ^ (row & 7);
            offB[kk][j] = (uint32_t)(16384 + row * 128 + sw * 16);
        }
    }

    const __nv_bfloat16* Ag = A    + (size_t)bm * Ktot;
    const __nv_bfloat16* Bg = Bmat + (size_t)bn * Ktot;

    float acc[4][8][4];
    #pragma unroll
    for (int i = 0; i < 4; ++i)
        #pragma unroll
        for (int j = 0; j < 8; ++j)
            #pragma unroll
            for (int r = 0; r < 4; ++r) acc[i][j][r] = 0.f;

    const int NK = Ktot >> 6;
    const uint32_t SST = 32768u;

    #pragma unroll
    for (int s = 0; s < 2; ++s) {
        uint32_t sb = sbase + (uint32_t)s * SST;
        int k0 = s << 6;
        #pragma unroll
        for (int i = 0; i < 8; ++i) {
            int flat = tid + (i << 7);
            int row = flat >> 3, ch = flat & 7;
            uint32_t so = (uint32_t)(row * 128 + ((ch ^ (row & 7)) << 4));
            const void* pa = Ag + (size_t)row * Ktot + k0 + (ch << 3);
            asm volatile("cp.async.cg.shared.global [%0], [%1], 16;" :: "r"(sb + so), "l"(pa));
            const void* pb = Bg + (size_t)row * Ktot + k0 + (ch << 3);
            asm volatile("cp.async.cg.shared.global [%0], [%1], 16;" :: "r"(sb + 16384u + so), "l"(pb));
        }
        asm volatile("cp.async.commit_group;" ::: "memory");
    }

    for (int it = 0; it < NK; ++it) {
        if (it < NK - 1) asm volatile("cp.async.wait_group 1;" ::: "memory");
        else             asm volatile("cp.async.wait_group 0;" ::: "memory");
        __syncthreads();

        if (it + 2 < NK) {
            uint32_t sb2 = sbase + (uint32_t)((it + 2) % 3) * SST;
            int k0 = (it + 2) << 6;
            #pragma unroll
            for (int i = 0; i < 8; ++i) {
                int flat = tid + (i << 7);
                int row = flat >> 3, ch = flat & 7;
                uint32_t so = (uint32_t)(row * 128 + ((ch ^ (row & 7)) << 4));
                const void* pa = Ag + (size_t)row * Ktot + k0 + (ch << 3);
                asm volatile("cp.async.cg.shared.global [%0], [%1], 16;" :: "r"(sb2 + so), "l"(pa));
                const void* pb = Bg + (size_t)row * Ktot + k0 + (ch << 3);
                asm volatile("cp.async.cg.shared.global [%0], [%1], 16;" :: "r"(sb2 + 16384u + so), "l"(pb));
            }
            asm volatile("cp.async.commit_group;" ::: "memory");
        }

        const uint32_t sb = sbase + (uint32_t)(it % 3) * SST;
        #pragma unroll
        for (int kk = 0; kk < 4; ++kk) {
            const uint32_t xm = (kk & 2) ? 64u : 0u;
            const int ki = kk & 1;
            uint32_t a[4][4], b[4][4];
            #pragma unroll
            for (int i = 0; i < 4; ++i)
                ldsm4(a[i][0], a[i][1], a[i][2], a[i][3], sb + (offA[ki][i] ^ xm));
            #pragma unroll
            for (int j = 0; j < 4; ++j)
                ldsm4(b[j][0], b[j][1], b[j][2], b[j][3], sb + (offB[ki][j] ^ xm));
            #pragma unroll
            for (int i = 0; i < 4; ++i)
                #pragma unroll
                for (int j = 0; j < 8; ++j)
                    mma16816(acc[i][j], a[i], b[j >> 1][(j & 1) * 2 + 0], b[j >> 1][(j & 1) * 2 + 1]);
        }
    }

    const int qid = lane >> 2;
    const int ql  = (lane & 3) << 1;
    #pragma unroll
    for (int i = 0; i < 4; ++i) {
        const int gp0 = bm + wm + i * 16 + qid;
        #pragma unroll
        for (int j = 0; j < 8; ++j) {
            const int gq = bn + wn + j * 8 + ql;
            const size_t o0 = (size_t)gp0 * Nld + gq;
            const size_t o1 = o0 + (size_t)8 * Nld;
            *(float2*)(Out + o0) = make_float2(acc[i][j][0], acc[i][j][1]);
            *(float2*)(Out + o1) = make_float2(acc[i][j][2], acc[i][j][3]);
        }
    }
}

// ============================================================
// launch  (4 launches total)
// ============================================================
extern "C" void kernel_launch(void* const* d_in, const int* in_sizes, int n_in,
                              void* d_out, int out_size)
{
    const float* pre_sp  = (const float*)d_in[0];
    const float* post_sp = (const float*)d_in[1];
    const float* W       = (const float*)d_in[2];
    const float* pre_tr  = (const float*)d_in[3];
    const float* post_tr = (const float*)d_in[4];
    const float* rr      = (const float*)d_in[5];

    float* out = (float*)d_out;
    float* cur      = out;
    float* wn       = cur + (size_t)BB * POSTN;
    float* new_pre  = wn + (size_t)POSTN * PREN;
    float* new_post = new_pre + (size_t)BB * PREN;
    float* new_rate = new_post + (size_t)BB * POSTN;

    void *pA, *pB, *pPre, *pWb;
    cudaGetSymbolAddress(&pA,   g_A);
    cudaGetSymbolAddress(&pB,   g_Bm);
    cudaGetSymbolAddress(&pPre, g_preb);
    cudaGetSymbolAddress(&pWb,  g_Wb);

    const int SMEM1 = 4 * 16384;   // 64KB (wupdate GEMM path)
    const int SMEM2 = 3 * 32768;   // 96KB (gemm2)
    cudaFuncSetAttribute(wupdate_mma, cudaFuncAttributeMaxDynamicSharedMemorySize, SMEM1);
    cudaFuncSetAttribute(gemm2_mma,   cudaFuncAttributeMaxDynamicSharedMemorySize, SMEM2);

    // launch 0: traces + bf16(pre_spikes) + flag detection
    {
        long long n_pre4  = (long long)BB * PREN / 4;
        long long n_post4 = (long long)BB * POSTN / 4;
        prep_ew<<<2048, 256>>>((const float4*)pre_sp, (const float4*)pre_tr,
                               (const float4*)post_sp, (const float4*)post_tr,
                               (float4*)new_pre, (float4*)new_post,
                               (uint2*)pPre, n_pre4, n_post4);
    }

    // launch 1: K-major bf16 transposes (self-gated)
    {
        const float S0 = (A_PLUS * DECAYF) / (float)BB;
        const float S1 = -(A_MINUS * DECAYF) / (float)BB;
        dim3 g(4096 / 64, BB / 64);
        prep_tr4<<<g, 256>>>(post_sp, post_tr, pre_tr, pre_sp,
                             (__nv_bfloat16*)pA, (__nv_bfloat16*)pB, S0, S1);
    }

    // launch 2: weight update + fused rate partials
    {
        dim3 grid(PREN / 128, POSTN / 128);
        wupdate_mma<<<grid, 256, SMEM1>>>((const __nv_bfloat16*)pA,
                                          (const __nv_bfloat16*)pB,
                                          post_sp, W, rr, wn,
                                          (__nv_bfloat16*)pWb, K1, PREN);
    }

    // launch 3 (profiled slot): current GEMM + spread rate EMA + flag reset
    {
        dim3 grid(POSTN / 128, BB / 128);
        gemm2_mma<<<grid, 128, SMEM2>>>((const __nv_bfloat16*)pPre,
                                        (const __nv_bfloat16*)pWb,
                                        rr, new_rate, cur, PREN, POSTN);
    }
}